// round 14
// baseline (speedup 1.0000x reference)
#include <cuda_runtime.h>
#include <cuda_bf16.h>
#include <math.h>
#include <stdint.h>

#define BB 4
#define TT 1024
#define SS 1024
#define DD 1024
#define HH 16
#define DKD 64
#define DFFN 4096
#define LN_EPS 1e-6f

// ===================== scratch (no allocations) =====================
__device__ float g_q [BB*TT*DD];
__device__ float g_k [BB*TT*DD];
__device__ float g_v [BB*TT*DD];
__device__ float g_t1[BB*TT*DD];
__device__ float g_x1[BB*TT*DD];
__device__ float g_x2[BB*TT*DD];
__device__ float g_st[64ULL * 1024 * 2];          // per (z,q): max, inv_sum

__device__ __nv_bfloat16 g_a2 [4096ULL * 2048];   // activations [M,2K] (hi|lo)
__device__ __nv_bfloat16 g_ff2[4096ULL * 8192];   // FF activations (hi|lo)
__device__ __nv_bfloat16 g_vt2[4096ULL * 2048];   // V^T split per (b,h): [64 d][hi|lo seq]
#define W2D (1024ULL*2048)
#define W1OFF (8*W2D)
#define W2OFF (8*W2D + 4096ULL*2048)
__device__ __nv_bfloat16 g_wt2[8*W2D + 4096ULL*2048 + 1024ULL*8192];

// ===================== helpers =====================
__device__ __forceinline__ uint32_t pack_hi2(float x, float y) {
    __nv_bfloat16 a = __float2bfloat16(x), b = __float2bfloat16(y);
    return (uint32_t)__bfloat16_as_ushort(a) | ((uint32_t)__bfloat16_as_ushort(b) << 16);
}
__device__ __forceinline__ uint32_t pack_lo2(float x, float y) {
    __nv_bfloat16 a = __float2bfloat16(x), b = __float2bfloat16(y);
    __nv_bfloat16 ra = __float2bfloat16(x - __bfloat162float(a));
    __nv_bfloat16 rb = __float2bfloat16(y - __bfloat162float(b));
    return (uint32_t)__bfloat16_as_ushort(ra) | ((uint32_t)__bfloat16_as_ushort(rb) << 16);
}
__device__ __forceinline__ void mma_bf16(
    float* d, const uint32_t* a, const uint32_t* b)
{
    asm volatile(
        "mma.sync.aligned.m16n8k16.row.col.f32.bf16.bf16.f32 "
        "{%0,%1,%2,%3}, {%4,%5,%6,%7}, {%8,%9}, {%0,%1,%2,%3};"
        : "+f"(d[0]), "+f"(d[1]), "+f"(d[2]), "+f"(d[3])
        : "r"(a[0]), "r"(a[1]), "r"(a[2]), "r"(a[3]), "r"(b[0]), "r"(b[1]));
}
__device__ __forceinline__ uint32_t smem_u32(const void* p) {
    uint32_t a;
    asm("{ .reg .u64 t; cvta.to.shared.u64 t, %1; cvt.u32.u64 %0, t; }" : "=r"(a) : "l"(p));
    return a;
}
__device__ __forceinline__ void cp16(uint32_t s, const void* g) {
    asm volatile("cp.async.cg.shared.global [%0], [%1], 16;" :: "r"(s), "l"(g));
}
#define CP_COMMIT() asm volatile("cp.async.commit_group;" ::: "memory")
#define CP_WAIT1()  asm volatile("cp.async.wait_group 1;" ::: "memory")
__device__ __forceinline__ void ldm4(uint32_t& r0, uint32_t& r1, uint32_t& r2, uint32_t& r3, uint32_t a) {
    asm volatile("ldmatrix.sync.aligned.m8n8.x4.shared.b16 {%0,%1,%2,%3}, [%4];"
        : "=r"(r0), "=r"(r1), "=r"(r2), "=r"(r3) : "r"(a));
}

// ===================== split/convert kernels =====================
__global__ __launch_bounds__(256) void split_act(
    const float* __restrict__ A, __nv_bfloat16* __restrict__ O)
{
    const int K = 1024;
    size_t idx = (size_t)blockIdx.x * 256 + threadIdx.x;
    size_t base = idx << 2;
    size_t m = base >> 10;
    int k = (int)(base & (size_t)(K - 1));
    float4 v = *(const float4*)(A + base);
    uint2 hh, ll;
    hh.x = pack_hi2(v.x, v.y); hh.y = pack_hi2(v.z, v.w);
    ll.x = pack_lo2(v.x, v.y); ll.y = pack_lo2(v.z, v.w);
    __nv_bfloat16* row = O + m * (size_t)(2 * K);
    *(uint2*)(row + k)     = hh;
    *(uint2*)(row + K + k) = ll;
}

__global__ void split_w(
    const float* __restrict__ W, __nv_bfloat16* __restrict__ O, int K, int N)
{
    __shared__ float t[32][33];
    int k = blockIdx.y * 32 + threadIdx.y;
    int n = blockIdx.x * 32 + threadIdx.x;
    t[threadIdx.y][threadIdx.x] = W[(size_t)k * N + n];
    __syncthreads();
    int nn = blockIdx.x * 32 + threadIdx.y;
    int kk = blockIdx.y * 32 + threadIdx.x;
    float v = t[threadIdx.x][threadIdx.y];
    __nv_bfloat16 h = __float2bfloat16(v);
    __nv_bfloat16 l = __float2bfloat16(v - __bfloat162float(h));
    size_t ro = (size_t)nn * (size_t)(2 * K);
    O[ro + kk]     = h;
    O[ro + K + kk] = l;
}

__global__ void vt_split(
    const float* __restrict__ V, __nv_bfloat16* __restrict__ VT2)
{
    __shared__ float t[32][33];
    const int b = blockIdx.z;
    int k = blockIdx.x * 32 + threadIdx.y;
    int d = blockIdx.y * 32 + threadIdx.x;
    t[threadIdx.y][threadIdx.x] = V[((size_t)(b * TT + k)) * DD + d];
    __syncthreads();
    int dg = blockIdx.y * 32 + threadIdx.y;
    int kg = blockIdx.x * 32 + threadIdx.x;
    float v = t[threadIdx.x][threadIdx.y];
    __nv_bfloat16 h = __float2bfloat16(v);
    __nv_bfloat16 l = __float2bfloat16(v - __bfloat162float(h));
    int hh = dg >> 6, dk = dg & 63;
    size_t row = ((size_t)(b * HH + hh) * 64 + dk) * 2048;
    VT2[row + kg]        = h;
    VT2[row + 1024 + kg] = l;
}

// ===================== HMMA GEMM, 2-segment operands, 3 products in-smem ====
#define PADK2 72
#define TSTG (128 * PADK2 * 2)
#define SSTG (2 * TSTG)
#define STAGES2 3
#define GEMM_SMEM (STAGES2 * SSTG)

__global__ __launch_bounds__(256) void gemm_mma(
    const __nv_bfloat16* __restrict__ A2, const __nv_bfloat16* __restrict__ W2,
    const float* __restrict__ bias, float* __restrict__ C,
    __nv_bfloat16* __restrict__ O3, int N, int Kl, int relu)
{
    extern __shared__ char dsm[];
    const uint32_t sb = smem_u32(dsm);
    const int tid = threadIdx.x;
    const int lane = tid & 31, wid = tid >> 5;
    const int wm = wid >> 2, wn = wid & 3;
    const int grp = lane >> 2, tg = lane & 3;

    const size_t arow0 = (size_t)blockIdx.y * 128;
    const size_t bcol0 = (size_t)blockIdx.x * 128;
    const size_t rstr = (size_t)2 * Kl;

    const uint32_t aLM = (uint32_t)(((wm * 64) + (lane & 15)) * PADK2 + (lane >> 4) * 8) * 2;
    const uint32_t bLM = (uint32_t)(((wn * 32) + (lane & 15)) * PADK2 + (lane >> 4) * 8) * 2;

    float acc[4][4][4];
    #pragma unroll
    for (int i = 0; i < 4; i++)
        #pragma unroll
        for (int j = 0; j < 4; j++)
            #pragma unroll
            for (int q = 0; q < 4; q++) acc[i][j][q] = 0.f;

    const int NC = Kl >> 5;

    auto issue = [&](int c, int st) {
        const uint32_t ab = sb + st * SSTG;
        const uint32_t bb = ab + TSTG;
        #pragma unroll
        for (int i = 0; i < 4; i++) {
            int idx = tid + i * 256;
            int r = idx >> 3, s = idx & 7;
            size_t go = (s < 4) ? ((size_t)c * 32 + s * 8)
                                : ((size_t)Kl + c * 32 + (s - 4) * 8);
            uint32_t so = (uint32_t)(r * PADK2 + s * 8) * 2;
            cp16(ab + so, A2 + (arow0 + r) * rstr + go);
            cp16(bb + so, W2 + (bcol0 + r) * rstr + go);
        }
        CP_COMMIT();
    };

    issue(0, 0); issue(1, 1);

    int st = 0;
    for (int c = 0; c < NC; c++) {
        CP_WAIT1();
        __syncthreads();
        if (c + 2 < NC) {
            int ns = st + 2; if (ns >= 3) ns -= 3;
            issue(c + 2, ns);
        } else CP_COMMIT();

        const uint32_t As0 = sb + st * SSTG;
        const uint32_t Bs0 = As0 + TSTG;
        #pragma unroll
        for (int ks = 0; ks < 2; ks++) {
            const uint32_t ko = ks * 32;
            uint32_t ah[4][4], al[4][4], b2[4][2];
            #pragma unroll
            for (int ms = 0; ms < 4; ms++)
                ldm4(ah[ms][0], ah[ms][1], ah[ms][2], ah[ms][3],
                     As0 + aLM + ms * (16 * PADK2 * 2) + ko);
            ldm4(b2[0][0], b2[1][0], b2[0][1], b2[1][1], Bs0 + bLM + ko);
            ldm4(b2[2][0], b2[3][0], b2[2][1], b2[3][1], Bs0 + bLM + 16 * PADK2 * 2 + ko);
            #pragma unroll
            for (int ms = 0; ms < 4; ms++)
                #pragma unroll
                for (int ns = 0; ns < 4; ns++)
                    mma_bf16(acc[ms][ns], ah[ms], b2[ns]);
            #pragma unroll
            for (int ms = 0; ms < 4; ms++)
                ldm4(al[ms][0], al[ms][1], al[ms][2], al[ms][3],
                     As0 + aLM + ms * (16 * PADK2 * 2) + ko + 64);
            #pragma unroll
            for (int ms = 0; ms < 4; ms++)
                #pragma unroll
                for (int ns = 0; ns < 4; ns++)
                    mma_bf16(acc[ms][ns], al[ms], b2[ns]);
            ldm4(b2[0][0], b2[1][0], b2[0][1], b2[1][1], Bs0 + bLM + ko + 64);
            ldm4(b2[2][0], b2[3][0], b2[2][1], b2[3][1], Bs0 + bLM + 16 * PADK2 * 2 + ko + 64);
            #pragma unroll
            for (int ms = 0; ms < 4; ms++)
                #pragma unroll
                for (int ns = 0; ns < 4; ns++)
                    mma_bf16(acc[ms][ns], ah[ms], b2[ns]);
        }
        if (++st >= 3) st = 0;
    }

    if (O3) {
        const size_t ostr = (size_t)2 * N;
        #pragma unroll
        for (int ms = 0; ms < 4; ms++) {
            const size_t rr0 = arow0 + wm * 64 + ms * 16 + grp;
            #pragma unroll
            for (int ns = 0; ns < 4; ns++) {
                const size_t cc = bcol0 + wn * 32 + ns * 8 + tg * 2;
                float bx = bias[cc], by = bias[cc + 1];
                float v0 = fmaxf(acc[ms][ns][0] + bx, 0.f);
                float v1 = fmaxf(acc[ms][ns][1] + by, 0.f);
                float v2 = fmaxf(acc[ms][ns][2] + bx, 0.f);
                float v3 = fmaxf(acc[ms][ns][3] + by, 0.f);
                __nv_bfloat16* R0 = O3 + rr0 * ostr;
                __nv_bfloat16* R1 = O3 + (rr0 + 8) * ostr;
                *(uint32_t*)(R0 + cc)     = pack_hi2(v0, v1);
                *(uint32_t*)(R0 + N + cc) = pack_lo2(v0, v1);
                *(uint32_t*)(R1 + cc)     = pack_hi2(v2, v3);
                *(uint32_t*)(R1 + N + cc) = pack_lo2(v2, v3);
            }
        }
    } else {
        #pragma unroll
        for (int ms = 0; ms < 4; ms++) {
            const size_t rr0 = arow0 + wm * 64 + ms * 16 + grp;
            #pragma unroll
            for (int ns = 0; ns < 4; ns++) {
                const size_t cc = bcol0 + wn * 32 + ns * 8 + tg * 2;
                float bx = bias[cc], by = bias[cc + 1];
                float v0 = acc[ms][ns][0] + bx;
                float v1 = acc[ms][ns][1] + by;
                float v2 = acc[ms][ns][2] + bx;
                float v3 = acc[ms][ns][3] + by;
                if (relu) {
                    v0 = fmaxf(v0, 0.f); v1 = fmaxf(v1, 0.f);
                    v2 = fmaxf(v2, 0.f); v3 = fmaxf(v3, 0.f);
                }
                *(float2*)(C + rr0 * N + cc)       = make_float2(v0, v1);
                *(float2*)(C + (rr0 + 8) * N + cc) = make_float2(v2, v3);
            }
        }
    }
}

// ===================== attention scores + fused softmax stats ======
#define SPAD2 136
#define SCORES_SMEM ((128 + 64) * SPAD2 * 2 + 128 * 16 + 4096)
__global__ __launch_bounds__(256) void attn_scores_mma(
    const float* __restrict__ Q, const float* __restrict__ Kv,
    float* __restrict__ Sc, float* __restrict__ st,
    const int* __restrict__ mask, int causal)
{
    extern __shared__ __nv_bfloat16 sm[];
    __nv_bfloat16* As = sm;                 // [128][SPAD2]  Q: [hi|lo]
    __nv_bfloat16* Bs = sm + 128 * SPAD2;   // [64][SPAD2]   K: [hi|lo]
    float* stg = (float*)(sm + (128 + 64) * SPAD2);   // [128][2][2]
    int*   msk = (int*)(stg + 128 * 4);               // [1024]
    const int z = blockIdx.y, b = z >> 4, h = z & 15;
    const int q0 = blockIdx.x * 128;

    const int tid = threadIdx.x, lane = tid & 31, wid = tid >> 5;
    const int wm = wid >> 1, wn = wid & 1;
    const int grp = lane >> 2, tg = lane & 3;

    const float* Qb = Q + ((size_t)(b * TT + q0)) * DD + h * DKD;

    #pragma unroll
    for (int i = 0; i < 8; i++) {
        int f = tid + i * 256;
        int r = f >> 4, c = (f & 15) << 2;
        float4 v = *(const float4*)(Qb + (size_t)r * DD + c);
        uint2 hh, ll;
        hh.x = pack_hi2(v.x, v.y); hh.y = pack_hi2(v.z, v.w);
        ll.x = pack_lo2(v.x, v.y); ll.y = pack_lo2(v.z, v.w);
        __nv_bfloat16* R = As + r * SPAD2;
        *(uint2*)(R + c)      = hh;
        *(uint2*)(R + 64 + c) = ll;
    }
    if (!causal) {
        #pragma unroll
        for (int i = 0; i < 4; i++) msk[tid + i * 256] = mask[b * SS + tid + i * 256];
    }

    const uint32_t AsU = smem_u32(As), BsU = smem_u32(Bs);
    const uint32_t aLM = AsU + (uint32_t)(((wm * 32) + (lane & 15)) * SPAD2 + (lane >> 4) * 8) * 2;
    const uint32_t bLM = BsU + (uint32_t)(((wn * 32) + (lane & 15)) * SPAD2 + (lane >> 4) * 8) * 2;

    float ms_[2][2] = {{-3.0e38f, -3.0e38f}, {-3.0e38f, -3.0e38f}};
    float ss_[2][2] = {{0.f, 0.f}, {0.f, 0.f}};
    const int ktend = causal ? ((q0 >> 6) + 2) : 16;

    for (int kt = 0; kt < ktend; kt++) {
        const int k0 = kt * 64;
        __syncthreads();
        const float* Kb = Kv + ((size_t)(b * TT + k0)) * DD + h * DKD;
        #pragma unroll
        for (int i = 0; i < 4; i++) {
            int f = tid + i * 256;
            int r = f >> 4, c = (f & 15) << 2;
            float4 v = *(const float4*)(Kb + (size_t)r * DD + c);
            uint2 hh, ll;
            hh.x = pack_hi2(v.x, v.y); hh.y = pack_hi2(v.z, v.w);
            ll.x = pack_lo2(v.x, v.y); ll.y = pack_lo2(v.z, v.w);
            __nv_bfloat16* R = Bs + r * SPAD2;
            *(uint2*)(R + c)      = hh;
            *(uint2*)(R + 64 + c) = ll;
        }
        __syncthreads();

        float acc[2][4][4];
        #pragma unroll
        for (int i = 0; i < 2; i++)
            #pragma unroll
            for (int j = 0; j < 4; j++)
                #pragma unroll
                for (int q = 0; q < 4; q++) acc[i][j][q] = 0.f;

        #pragma unroll
        for (int ks = 0; ks < 4; ks++) {
            const uint32_t ko = ks * 32;
            uint32_t ah[2][4], al[2][4], bb[4][2];
            #pragma unroll
            for (int mi = 0; mi < 2; mi++)
                ldm4(ah[mi][0], ah[mi][1], ah[mi][2], ah[mi][3],
                     aLM + mi * (16 * SPAD2 * 2) + ko);
            ldm4(bb[0][0], bb[1][0], bb[0][1], bb[1][1], bLM + ko);
            ldm4(bb[2][0], bb[3][0], bb[2][1], bb[3][1], bLM + 16 * SPAD2 * 2 + ko);
            #pragma unroll
            for (int mi = 0; mi < 2; mi++)
                #pragma unroll
                for (int ni = 0; ni < 4; ni++)
                    mma_bf16(acc[mi][ni], ah[mi], bb[ni]);
            #pragma unroll
            for (int mi = 0; mi < 2; mi++)
                ldm4(al[mi][0], al[mi][1], al[mi][2], al[mi][3],
                     aLM + mi * (16 * SPAD2 * 2) + ko + 128);
            #pragma unroll
            for (int mi = 0; mi < 2; mi++)
                #pragma unroll
                for (int ni = 0; ni < 4; ni++)
                    mma_bf16(acc[mi][ni], al[mi], bb[ni]);
            ldm4(bb[0][0], bb[1][0], bb[0][1], bb[1][1], bLM + ko + 128);
            ldm4(bb[2][0], bb[3][0], bb[2][1], bb[3][1], bLM + 16 * SPAD2 * 2 + ko + 128);
            #pragma unroll
            for (int mi = 0; mi < 2; mi++)
                #pragma unroll
                for (int ni = 0; ni < 4; ni++)
                    mma_bf16(acc[mi][ni], ah[mi], bb[ni]);
        }

        float* Out = Sc + ((size_t)z * TT + q0) * TT + k0;
        #pragma unroll
        for (int mi = 0; mi < 2; mi++) {
            const size_t r = wm * 32 + mi * 16 + grp;
            #pragma unroll
            for (int ni = 0; ni < 4; ni++) {
                const size_t c = wn * 32 + ni * 8 + tg * 2;
                *(float2*)(Out + r * TT + c) =
                    make_float2(acc[mi][ni][0] * 0.125f, acc[mi][ni][1] * 0.125f);
                *(float2*)(Out + (r + 8) * TT + c) =
                    make_float2(acc[mi][ni][2] * 0.125f, acc[mi][ni][3] * 0.125f);
            }
        }
        #pragma unroll
        for (int mi = 0; mi < 2; mi++) {
            #pragma unroll
            for (int half = 0; half < 2; half++) {
                const int q = q0 + wm * 32 + mi * 16 + half * 8 + grp;
                float vv[8];
                float tm = -3.0e38f;
                #pragma unroll
                for (int ni = 0; ni < 4; ni++) {
                    #pragma unroll
                    for (int e = 0; e < 2; e++) {
                        int k = k0 + wn * 32 + ni * 8 + tg * 2 + e;
                        float v = acc[mi][ni][half * 2 + e] * 0.125f;
                        int valid = causal ? (k <= q) : msk[k];
                        v = valid ? v : -1e9f;
                        vv[ni * 2 + e] = v;
                        tm = fmaxf(tm, v);
                    }
                }
                float m = ms_[mi][half];
                float nm = fmaxf(m, tm);
                float as = 0.f;
                #pragma unroll
                for (int i = 0; i < 8; i++) as += __expf(vv[i] - nm);
                ss_[mi][half] = ss_[mi][half] * __expf(m - nm) + as;
                ms_[mi][half] = nm;
            }
        }
    }

    #pragma unroll
    for (int mi = 0; mi < 2; mi++) {
        #pragma unroll
        for (int half = 0; half < 2; half++) {
            float m = ms_[mi][half], s = ss_[mi][half];
            #pragma unroll
            for (int o = 1; o <= 2; o <<= 1) {
                float mo = __shfl_xor_sync(0xffffffffu, m, o);
                float so = __shfl_xor_sync(0xffffffffu, s, o);
                float nm = fmaxf(m, mo);
                s = s * __expf(m - nm) + so * __expf(mo - nm);
                m = nm;
            }
            if (tg == 0) {
                int row = wm * 32 + mi * 16 + half * 8 + grp;
                stg[(row * 2 + wn) * 2]     = m;
                stg[(row * 2 + wn) * 2 + 1] = s;
            }
        }
    }
    __syncthreads();
    if (tid < 128) {
        float m0 = stg[(tid * 2) * 2],     s0 = stg[(tid * 2) * 2 + 1];
        float m1 = stg[(tid * 2 + 1) * 2], s1 = stg[(tid * 2 + 1) * 2 + 1];
        float M = fmaxf(m0, m1);
        float S = s0 * __expf(m0 - M) + s1 * __expf(m1 - M);
        st[((size_t)z * TT + q0 + tid) * 2]     = M;
        st[((size_t)z * TT + q0 + tid) * 2 + 1] = 1.0f / S;
    }
}

// ===================== attn @ V, fused softmax-apply, 128-wide k tiles ======
#define SPAD3 264
#define AV_SMEM ((64 + 64) * SPAD3 * 2 + 512)
__global__ __launch_bounds__(256) void attn_av_mma(
    float* __restrict__ Sc, const __nv_bfloat16* __restrict__ VT2,
    const float* __restrict__ st, const int* __restrict__ mask,
    __nv_bfloat16* __restrict__ A2out, int causal)
{
    extern __shared__ __nv_bfloat16 sm[];
    __nv_bfloat16* As = sm;                // [64 q][SPAD3]  P: hi[0,kw) lo[kw,2kw)
    __nv_bfloat16* Bs = sm + 64 * SPAD3;   // [64 d][SPAD3]  V^T: same layout
    float* stats = (float*)(sm + 128 * SPAD3);
    const int z = blockIdx.y, b = z >> 4, h = z & 15;
    const int q0 = blockIdx.x * 64;

    const int tid = threadIdx.x, lane = tid & 31, wid = tid >> 5;
    const int wm = wid >> 1, wn = wid & 1;
    const int grp = lane >> 2, tg = lane & 3;

    const int kend = causal ? (q0 + 64) : TT;

    if (tid < 64) {
        stats[tid]      = st[((size_t)z * TT + q0 + tid) * 2];
        stats[64 + tid] = st[((size_t)z * TT + q0 + tid) * 2 + 1];
    }
    __syncthreads();

    const __nv_bfloat16* Vt = VT2 + (size_t)z * 64 * 2048;
    const uint32_t AsU = smem_u32(As), BsU = smem_u32(Bs);
    const uint32_t aLM = AsU + (uint32_t)(((wm * 16) + (lane & 15)) * SPAD3 + (lane >> 4) * 8) * 2;
    const uint32_t bLM = BsU + (uint32_t)(((wn * 32) + (lane & 15)) * SPAD3 + (lane >> 4) * 8) * 2;

    float acc[4][4];
    #pragma unroll
    for (int i = 0; i < 4; i++)
        #pragma unroll
        for (int j = 0; j < 4; j++) acc[i][j] = 0.f;

    for (int k0 = 0; k0 < kend; k0 += 128) {
        const int kw  = (kend - k0 >= 128) ? 128 : 64;
        const int kws = (kw == 128) ? 5 : 4;       // log2(kw/4)
        const int kwq = kw >> 2;
        float* Pb = Sc + ((size_t)z * TT + q0) * TT + k0;

        // P apply + convert: 64 rows x kw cols
        const int nit = (64 * kw) >> 10;            // 8 or 4
        for (int i = 0; i < nit; i++) {
            int f = tid + i * 256;
            int r = f >> kws, c = (f & (kwq - 1)) << 2;
            float4 pv = *(float4*)(Pb + (size_t)r * TT + c);
            const int qabs = q0 + r;
            const int kg = k0 + c;
            float v0, v1, v2, v3;
            if (causal) {
                v0 = (kg     <= qabs) ? pv.x : -1e9f;
                v1 = (kg + 1 <= qabs) ? pv.y : -1e9f;
                v2 = (kg + 2 <= qabs) ? pv.z : -1e9f;
                v3 = (kg + 3 <= qabs) ? pv.w : -1e9f;
            } else {
                int4 mk = *(const int4*)(mask + b * SS + kg);
                v0 = mk.x ? pv.x : -1e9f;
                v1 = mk.y ? pv.y : -1e9f;
                v2 = mk.z ? pv.z : -1e9f;
                v3 = mk.w ? pv.w : -1e9f;
            }
            const float mm = stats[r], iv = stats[64 + r];
            float p0 = __expf(v0 - mm) * iv;
            float p1 = __expf(v1 - mm) * iv;
            float p2 = __expf(v2 - mm) * iv;
            float p3 = __expf(v3 - mm) * iv;
            *(float4*)(Pb + (size_t)r * TT + c) = make_float4(p0, p1, p2, p3);
            uint2 hh, ll;
            hh.x = pack_hi2(p0, p1); hh.y = pack_hi2(p2, p3);
            ll.x = pack_lo2(p0, p1); ll.y = pack_lo2(p2, p3);
            __nv_bfloat16* R = As + r * SPAD3;
            *(uint2*)(R + c)      = hh;
            *(uint2*)(R + kw + c) = ll;
        }
        // V copy: hi + lo bands, 64 d rows x kw cols each
        const int nv = kw >> 5;                     // 4 or 2
        const int ps = kws - 1;                     // log2(kw/8)
        const int pm = (kw >> 3) - 1;
        for (int i = 0; i < nv; i++) {
            int idx = tid + i * 256;
            int d = idx >> ps, j = (idx & pm) * 8;
            const __nv_bfloat16* Vr = Vt + (size_t)d * 2048 + k0 + j;
            __nv_bfloat16* Br = Bs + d * SPAD3 + j;
            *(uint4*)(Br)      = *(const uint4*)(Vr);
            *(uint4*)(Br + kw) = *(const uint4*)(Vr + 1024);
        }
        __syncthreads();

        const int nks = kw >> 4;                    // 8 or 4
        const uint32_t loB = (uint32_t)kw * 2;      // lo segment byte offset
        for (int ks = 0; ks < nks; ks++) {
            const uint32_t ko = ks * 32;
            uint32_t ah[4], al[4], bb[4][2];
            ldm4(ah[0], ah[1], ah[2], ah[3], aLM + ko);
            ldm4(bb[0][0], bb[1][0], bb[0][1], bb[1][1], bLM + ko);
            ldm4(bb[2][0], bb[3][0], bb[2][1], bb[3][1], bLM + 16 * SPAD3 * 2 + ko);
            #pragma unroll
            for (int ni = 0; ni < 4; ni++)
                mma_bf16(acc[ni], ah, bb[ni]);
            ldm4(al[0], al[1], al[2], al[3], aLM + ko + loB);
            #pragma unroll
            for (int ni = 0; ni < 4; ni++)
                mma_bf16(acc[ni], al, bb[ni]);
            ldm4(bb[0][0], bb[1][0], bb[0][1], bb[1][1], bLM + ko + loB);
            ldm4(bb[2][0], bb[3][0], bb[2][1], bb[3][1], bLM + 16 * SPAD3 * 2 + ko + loB);
            #pragma unroll
            for (int ni = 0; ni < 4; ni++)
                mma_bf16(acc[ni], ah, bb[ni]);
        }
        __syncthreads();
    }

    if (causal && kend < TT) {
        const int Z = TT - kend;
        const int zw = Z >> 2;
        const int n4 = 64 * zw;
        const float4 z4 = make_float4(0.f, 0.f, 0.f, 0.f);
        for (int i = tid; i < n4; i += 256) {
            int r = i / zw, c = kend + (i - r * zw) * 4;
            *(float4*)(Sc + ((size_t)z * TT + q0 + r) * TT + c) = z4;
        }
    }

    const size_t m0 = (size_t)b * TT + q0 + wm * 16 + grp;
    const size_t m1 = m0 + 8;
    __nv_bfloat16* R0 = A2out + m0 * 2048;
    __nv_bfloat16* R1 = A2out + m1 * 2048;
    #pragma unroll
    for (int ni = 0; ni < 4; ni++) {
        const int cc = h * DKD + wn * 32 + ni * 8 + tg * 2;
        float v0 = acc[ni][0], v1 = acc[ni][1];
        float v2 = acc[ni][2], v3 = acc[ni][3];
        *(uint32_t*)(R0 + cc)        = pack_hi2(v0, v1);
        *(uint32_t*)(R0 + 1024 + cc) = pack_lo2(v0, v1);
        *(uint32_t*)(R1 + cc)        = pack_hi2(v2, v3);
        *(uint32_t*)(R1 + 1024 + cc) = pack_lo2(v2, v3);
    }
}

// ===================== residual add + LayerNorm =====================
__global__ __launch_bounds__(256) void add_ln(
    const float* __restrict__ X, const float* __restrict__ Dl,
    const float* __restrict__ g, const float* __restrict__ be,
    float* __restrict__ O, __nv_bfloat16* __restrict__ S2)
{
    const int row = blockIdx.x;
    const float* x  = X  + (size_t)row * DD;
    const float* dl = Dl + (size_t)row * DD;
    const int tid = threadIdx.x;

    float v[4];
    float s = 0.f;
    #pragma unroll
    for (int i = 0; i < 4; i++) {
        int c = tid + i * 256;
        v[i] = x[c] + dl[c];
        s += v[i];
    }
    __shared__ float red[8];
    #pragma unroll
    for (int o = 16; o > 0; o >>= 1) s += __shfl_xor_sync(0xffffffffu, s, o);
    if ((tid & 31) == 0) red[tid >> 5] = s;
    __syncthreads();
    s = 0.f;
    #pragma unroll
    for (int w = 0; w < 8; w++) s += red[w];
    float mean = s * (1.0f / 1024.0f);

    float qq = 0.f;
    #pragma unroll
    for (int i = 0; i < 4; i++) { float d = v[i] - mean; qq += d * d; }
    __syncthreads();
    #pragma unroll
    for (int o = 16; o > 0; o >>= 1) qq += __shfl_xor_sync(0xffffffffu, qq, o);
    if ((tid & 31) == 0) red[tid >> 5] = qq;
    __syncthreads();
    qq = 0.f;
    #pragma unroll
    for (int w = 0; w < 8; w++) qq += red[w];

    float stdv = sqrtf(qq * (1.0f / 1023.0f));
    float inv = 1.0f / (stdv + LN_EPS);
    __nv_bfloat16* R = S2 ? (S2 + (size_t)row * 2048) : (__nv_bfloat16*)0;
    #pragma unroll
    for (int i = 0; i < 4; i++) {
        int c = tid + i * 256;
        float o = g[c] * (v[i] - mean) * inv + be[c];
        O[(size_t)row * DD + c] = o;
        if (R) {
            __nv_bfloat16 h = __float2bfloat16(o);
            __nv_bfloat16 l = __float2bfloat16(o - __bfloat162float(h));
            R[c]        = h;
            R[1024 + c] = l;
        }
    }
}

// ===================== orchestration =====================
extern "C" void kernel_launch(void* const* d_in, const int* in_sizes, int n_in,
                              void* d_out, int out_size)
{
    const float* x        = (const float*)d_in[0];
    const float* enc      = (const float*)d_in[1];
    const int*   src_mask = (const int*)  d_in[2];
    const float* wq_s = (const float*)d_in[4],  *bq_s = (const float*)d_in[5];
    const float* wk_s = (const float*)d_in[6],  *bk_s = (const float*)d_in[7];
    const float* wv_s = (const float*)d_in[8],  *bv_s = (const float*)d_in[9];
    const float* wo_s = (const float*)d_in[10], *bo_s = (const float*)d_in[11];
    const float* wq_c = (const float*)d_in[12], *bq_c = (const float*)d_in[13];
    const float* wk_c = (const float*)d_in[14], *bk_c = (const float*)d_in[15];
    const float* wv_c = (const float*)d_in[16], *bv_c = (const float*)d_in[17];
    const float* wo_c = (const float*)d_in[18], *bo_c = (const float*)d_in[19];
    const float* w1   = (const float*)d_in[20], *b1   = (const float*)d_in[21];
    const float* w2   = (const float*)d_in[22], *b2   = (const float*)d_in[23];
    const float* g1   = (const float*)d_in[24], *be1  = (const float*)d_in[25];
    const float* g2   = (const float*)d_in[26], *be2  = (const float*)d_in[27];
    const float* g3   = (const float*)d_in[28], *be3  = (const float*)d_in[29];

    float* out     = (float*)d_out;
    float* self_w  = out + (size_t)BB * TT * DD;
    float* cross_w = self_w + (size_t)BB * HH * TT * TT;

    float *Q, *K, *V, *T1, *X1, *X2, *ST;
    __nv_bfloat16 *A2, *FF2, *WT2, *VT2;
    cudaGetSymbolAddress((void**)&Q,   g_q);
    cudaGetSymbolAddress((void**)&K,   g_k);
    cudaGetSymbolAddress((void**)&V,   g_v);
    cudaGetSymbolAddress((void**)&T1,  g_t1);
    cudaGetSymbolAddress((void**)&X1,  g_x1);
    cudaGetSymbolAddress((void**)&X2,  g_x2);
    cudaGetSymbolAddress((void**)&ST,  g_st);
    cudaGetSymbolAddress((void**)&A2,  g_a2);
    cudaGetSymbolAddress((void**)&FF2, g_ff2);
    cudaGetSymbolAddress((void**)&WT2, g_wt2);
    cudaGetSymbolAddress((void**)&VT2, g_vt2);

    cudaFuncSetAttribute(gemm_mma,        cudaFuncAttributeMaxDynamicSharedMemorySize, GEMM_SMEM);
    cudaFuncSetAttribute(attn_scores_mma, cudaFuncAttributeMaxDynamicSharedMemorySize, SCORES_SMEM);
    cudaFuncSetAttribute(attn_av_mma,     cudaFuncAttributeMaxDynamicSharedMemorySize, AV_SMEM);

    const int M = BB * TT;
    dim3 blk(256);
    dim3 tp32(32, 32);
    dim3 gD(DD / 128, M / 128);
    dim3 gF(DFFN / 128, M / 128);
    dim3 scoreG(TT / 128, BB * HH);
    dim3 avG(TT / 64, BB * HH);
    dim3 vtG(TT / 32, DD / 32, BB);
    dim3 lnG(M);
    const int ACT_BLKS = M * DD / 4 / 256;
    float* NC = (float*)0;
    __nv_bfloat16* NO3 = (__nv_bfloat16*)0;

    // ---- self attention ----
    split_act<<<ACT_BLKS, blk>>>(x, A2);
    split_w<<<dim3(32, 32), tp32>>>(wq_s, WT2 + 0 * W2D, DD, DD);
    split_w<<<dim3(32, 32), tp32>>>(wk_s, WT2 + 1 * W2D, DD, DD);
    split_w<<<dim3(32, 32), tp32>>>(wv_s, WT2 + 2 * W2D, DD, DD);
    split_w<<<dim3(32, 32), tp32>>>(wo_s, WT2 + 3 * W2D, DD, DD);
    gemm_mma<<<gD, blk, GEMM_SMEM>>>(A2, WT2 + 0 * W2D, bq_s, Q, NO3, DD, 1024, 0);
    gemm_mma<<<gD, blk, GEMM_SMEM>>>(A2, WT2 + 1 * W2D, bk_s, K, NO3, DD, 1024, 0);
    gemm_mma<<<gD, blk, GEMM_SMEM>>>(A2, WT2 + 2 * W2D, bv_s, V, NO3, DD, 1024, 0);
    vt_split<<<vtG, tp32>>>(V, VT2);
    attn_scores_mma<<<scoreG, blk, SCORES_SMEM>>>(Q, K, self_w, ST, src_mask, 1);
    attn_av_mma<<<avG, blk, AV_SMEM>>>(self_w, VT2, ST, src_mask, A2, 1);
    gemm_mma<<<gD, blk, GEMM_SMEM>>>(A2, WT2 + 3 * W2D, bo_s, T1, NO3, DD, 1024, 0);
    add_ln<<<lnG, blk>>>(x, T1, g1, be1, X1, A2);

    // ---- remaining weight splits ----
    split_w<<<dim3(32, 32), tp32>>>(wq_c, WT2 + 4 * W2D, DD, DD);
    split_w<<<dim3(32, 32), tp32>>>(wk_c, WT2 + 5 * W2D, DD, DD);
    split_w<<<dim3(32, 32), tp32>>>(wv_c, WT2 + 6 * W2D, DD, DD);
    split_w<<<dim3(32, 32), tp32>>>(wo_c, WT2 + 7 * W2D, DD, DD);
    split_w<<<dim3(128, 32), tp32>>>(w1, WT2 + W1OFF, DD, DFFN);
    split_w<<<dim3(32, 128), tp32>>>(w2, WT2 + W2OFF, DFFN, DD);

    // ---- cross attention ----
    gemm_mma<<<gD, blk, GEMM_SMEM>>>(A2, WT2 + 4 * W2D, bq_c, Q, NO3, DD, 1024, 0);
    split_act<<<ACT_BLKS, blk>>>(enc, A2);
    gemm_mma<<<gD, blk, GEMM_SMEM>>>(A2, WT2 + 5 * W2D, bk_c, K, NO3, DD, 1024, 0);
    gemm_mma<<<gD, blk, GEMM_SMEM>>>(A2, WT2 + 6 * W2D, bv_c, V, NO3, DD, 1024, 0);
    vt_split<<<vtG, tp32>>>(V, VT2);
    attn_scores_mma<<<scoreG, blk, SCORES_SMEM>>>(Q, K, cross_w, ST, src_mask, 0);
    attn_av_mma<<<avG, blk, AV_SMEM>>>(cross_w, VT2, ST, src_mask, A2, 0);
    gemm_mma<<<gD, blk, GEMM_SMEM>>>(A2, WT2 + 7 * W2D, bo_c, T1, NO3, DD, 1024, 0);
    add_ln<<<lnG, blk>>>(X1, T1, g2, be2, X2, A2);

    // ---- feed-forward ----
    gemm_mma<<<gF, blk, GEMM_SMEM>>>(A2, WT2 + W1OFF, b1, NC, FF2, DFFN, 1024, 1);
    gemm_mma<<<gD, blk, GEMM_SMEM>>>(FF2, WT2 + W2OFF, b2, T1, NO3, DD, 4096, 0);
    add_ln<<<lnG, blk>>>(X2, T1, g3, be3, out, NO3);

    (void)in_sizes; (void)n_in; (void)out_size;
}

// round 15
// speedup vs baseline: 1.0353x; 1.0353x over previous
#include <cuda_runtime.h>
#include <cuda_bf16.h>
#include <math.h>
#include <stdint.h>

#define BB 4
#define TT 1024
#define SS 1024
#define DD 1024
#define HH 16
#define DKD 64
#define DFFN 4096
#define LN_EPS 1e-6f

// ===================== scratch (no allocations) =====================
__device__ float g_qkv[4096ULL * 3072];           // fused QKV (self) / Q + KV (cross)
__device__ float g_t1[BB*TT*DD];
__device__ float g_x1[BB*TT*DD];
__device__ float g_x2[BB*TT*DD];
__device__ float g_st[64ULL * 1024 * 2];          // per (z,q): max, inv_sum
__device__ float g_bs[3072];                      // concat bias self QKV
__device__ float g_bc[2048];                      // concat bias cross KV

__device__ __nv_bfloat16 g_a2 [4096ULL * 2048];   // activations [M,2K] (hi|lo)
__device__ __nv_bfloat16 g_ff2[4096ULL * 8192];   // FF activations (hi|lo)
__device__ __nv_bfloat16 g_vt2[4096ULL * 2048];   // V^T split per (b,h): [64 d][hi|lo seq]
#define W2D (1024ULL*2048)
#define W1OFF (8*W2D)
#define W2OFF (8*W2D + 4096ULL*2048)
__device__ __nv_bfloat16 g_wt2[8*W2D + 4096ULL*2048 + 1024ULL*8192];

// ===================== helpers =====================
__device__ __forceinline__ uint32_t pack_hi2(float x, float y) {
    __nv_bfloat16 a = __float2bfloat16(x), b = __float2bfloat16(y);
    return (uint32_t)__bfloat16_as_ushort(a) | ((uint32_t)__bfloat16_as_ushort(b) << 16);
}
__device__ __forceinline__ uint32_t pack_lo2(float x, float y) {
    __nv_bfloat16 a = __float2bfloat16(x), b = __float2bfloat16(y);
    __nv_bfloat16 ra = __float2bfloat16(x - __bfloat162float(a));
    __nv_bfloat16 rb = __float2bfloat16(y - __bfloat162float(b));
    return (uint32_t)__bfloat16_as_ushort(ra) | ((uint32_t)__bfloat16_as_ushort(rb) << 16);
}
__device__ __forceinline__ void mma_bf16(
    float* d, const uint32_t* a, const uint32_t* b)
{
    asm volatile(
        "mma.sync.aligned.m16n8k16.row.col.f32.bf16.bf16.f32 "
        "{%0,%1,%2,%3}, {%4,%5,%6,%7}, {%8,%9}, {%0,%1,%2,%3};"
        : "+f"(d[0]), "+f"(d[1]), "+f"(d[2]), "+f"(d[3])
        : "r"(a[0]), "r"(a[1]), "r"(a[2]), "r"(a[3]), "r"(b[0]), "r"(b[1]));
}
__device__ __forceinline__ uint32_t smem_u32(const void* p) {
    uint32_t a;
    asm("{ .reg .u64 t; cvta.to.shared.u64 t, %1; cvt.u32.u64 %0, t; }" : "=r"(a) : "l"(p));
    return a;
}
__device__ __forceinline__ void cp16(uint32_t s, const void* g) {
    asm volatile("cp.async.cg.shared.global [%0], [%1], 16;" :: "r"(s), "l"(g));
}
#define CP_COMMIT() asm volatile("cp.async.commit_group;" ::: "memory")
#define CP_WAIT1()  asm volatile("cp.async.wait_group 1;" ::: "memory")
__device__ __forceinline__ void ldm4(uint32_t& r0, uint32_t& r1, uint32_t& r2, uint32_t& r3, uint32_t a) {
    asm volatile("ldmatrix.sync.aligned.m8n8.x4.shared.b16 {%0,%1,%2,%3}, [%4];"
        : "=r"(r0), "=r"(r1), "=r"(r2), "=r"(r3) : "r"(a));
}

// ===================== split/convert kernels =====================
__global__ __launch_bounds__(256) void split_act(
    const float* __restrict__ A, __nv_bfloat16* __restrict__ O)
{
    const int K = 1024;
    size_t idx = (size_t)blockIdx.x * 256 + threadIdx.x;
    size_t base = idx << 2;
    size_t m = base >> 10;
    int k = (int)(base & (size_t)(K - 1));
    float4 v = *(const float4*)(A + base);
    uint2 hh, ll;
    hh.x = pack_hi2(v.x, v.y); hh.y = pack_hi2(v.z, v.w);
    ll.x = pack_lo2(v.x, v.y); ll.y = pack_lo2(v.z, v.w);
    __nv_bfloat16* row = O + m * (size_t)(2 * K);
    *(uint2*)(row + k)     = hh;
    *(uint2*)(row + K + k) = ll;
}

__global__ void split_w(
    const float* __restrict__ W, __nv_bfloat16* __restrict__ O, int K, int N)
{
    __shared__ float t[32][33];
    int k = blockIdx.y * 32 + threadIdx.y;
    int n = blockIdx.x * 32 + threadIdx.x;
    t[threadIdx.y][threadIdx.x] = W[(size_t)k * N + n];
    __syncthreads();
    int nn = blockIdx.x * 32 + threadIdx.y;
    int kk = blockIdx.y * 32 + threadIdx.x;
    float v = t[threadIdx.x][threadIdx.y];
    __nv_bfloat16 h = __float2bfloat16(v);
    __nv_bfloat16 l = __float2bfloat16(v - __bfloat162float(h));
    size_t ro = (size_t)nn * (size_t)(2 * K);
    O[ro + kk]     = h;
    O[ro + K + kk] = l;
}

__global__ void vt_split(
    const float* __restrict__ V, int vstr, __nv_bfloat16* __restrict__ VT2)
{
    __shared__ float t[32][33];
    const int b = blockIdx.z;
    int k = blockIdx.x * 32 + threadIdx.y;
    int d = blockIdx.y * 32 + threadIdx.x;
    t[threadIdx.y][threadIdx.x] = V[((size_t)(b * TT + k)) * vstr + d];
    __syncthreads();
    int dg = blockIdx.y * 32 + threadIdx.y;
    int kg = blockIdx.x * 32 + threadIdx.x;
    float v = t[threadIdx.x][threadIdx.y];
    __nv_bfloat16 h = __float2bfloat16(v);
    __nv_bfloat16 l = __float2bfloat16(v - __bfloat162float(h));
    int hh = dg >> 6, dk = dg & 63;
    size_t row = ((size_t)(b * HH + hh) * 64 + dk) * 2048;
    VT2[row + kg]        = h;
    VT2[row + 1024 + kg] = l;
}

// ===================== HMMA GEMM, 2-segment operands, 3 products in-smem ====
#define PADK2 72
#define TSTG (128 * PADK2 * 2)
#define SSTG (2 * TSTG)
#define STAGES2 3
#define GEMM_SMEM (STAGES2 * SSTG)

__global__ __launch_bounds__(256) void gemm_mma(
    const __nv_bfloat16* __restrict__ A2, const __nv_bfloat16* __restrict__ W2,
    const float* __restrict__ bias, float* __restrict__ C,
    __nv_bfloat16* __restrict__ O3, int N, int Kl, int relu)
{
    extern __shared__ char dsm[];
    const uint32_t sb = smem_u32(dsm);
    const int tid = threadIdx.x;
    const int lane = tid & 31, wid = tid >> 5;
    const int wm = wid >> 2, wn = wid & 3;
    const int grp = lane >> 2, tg = lane & 3;

    const size_t arow0 = (size_t)blockIdx.y * 128;
    const size_t bcol0 = (size_t)blockIdx.x * 128;
    const size_t rstr = (size_t)2 * Kl;

    const uint32_t aLM = (uint32_t)(((wm * 64) + (lane & 15)) * PADK2 + (lane >> 4) * 8) * 2;
    const uint32_t bLM = (uint32_t)(((wn * 32) + (lane & 15)) * PADK2 + (lane >> 4) * 8) * 2;

    float acc[4][4][4];
    #pragma unroll
    for (int i = 0; i < 4; i++)
        #pragma unroll
        for (int j = 0; j < 4; j++)
            #pragma unroll
            for (int q = 0; q < 4; q++) acc[i][j][q] = 0.f;

    const int NC = Kl >> 5;

    auto issue = [&](int c, int st) {
        const uint32_t ab = sb + st * SSTG;
        const uint32_t bb = ab + TSTG;
        #pragma unroll
        for (int i = 0; i < 4; i++) {
            int idx = tid + i * 256;
            int r = idx >> 3, s = idx & 7;
            size_t go = (s < 4) ? ((size_t)c * 32 + s * 8)
                                : ((size_t)Kl + c * 32 + (s - 4) * 8);
            uint32_t so = (uint32_t)(r * PADK2 + s * 8) * 2;
            cp16(ab + so, A2 + (arow0 + r) * rstr + go);
            cp16(bb + so, W2 + (bcol0 + r) * rstr + go);
        }
        CP_COMMIT();
    };

    issue(0, 0); issue(1, 1);

    int st = 0;
    for (int c = 0; c < NC; c++) {
        CP_WAIT1();
        __syncthreads();
        if (c + 2 < NC) {
            int ns = st + 2; if (ns >= 3) ns -= 3;
            issue(c + 2, ns);
        } else CP_COMMIT();

        const uint32_t As0 = sb + st * SSTG;
        const uint32_t Bs0 = As0 + TSTG;
        #pragma unroll
        for (int ks = 0; ks < 2; ks++) {
            const uint32_t ko = ks * 32;
            uint32_t ah[4][4], al[4][4], b2[4][2];
            #pragma unroll
            for (int ms = 0; ms < 4; ms++)
                ldm4(ah[ms][0], ah[ms][1], ah[ms][2], ah[ms][3],
                     As0 + aLM + ms * (16 * PADK2 * 2) + ko);
            ldm4(b2[0][0], b2[1][0], b2[0][1], b2[1][1], Bs0 + bLM + ko);
            ldm4(b2[2][0], b2[3][0], b2[2][1], b2[3][1], Bs0 + bLM + 16 * PADK2 * 2 + ko);
            #pragma unroll
            for (int ms = 0; ms < 4; ms++)
                #pragma unroll
                for (int ns = 0; ns < 4; ns++)
                    mma_bf16(acc[ms][ns], ah[ms], b2[ns]);
            #pragma unroll
            for (int ms = 0; ms < 4; ms++)
                ldm4(al[ms][0], al[ms][1], al[ms][2], al[ms][3],
                     As0 + aLM + ms * (16 * PADK2 * 2) + ko + 64);
            #pragma unroll
            for (int ms = 0; ms < 4; ms++)
                #pragma unroll
                for (int ns = 0; ns < 4; ns++)
                    mma_bf16(acc[ms][ns], al[ms], b2[ns]);
            ldm4(b2[0][0], b2[1][0], b2[0][1], b2[1][1], Bs0 + bLM + ko + 64);
            ldm4(b2[2][0], b2[3][0], b2[2][1], b2[3][1], Bs0 + bLM + 16 * PADK2 * 2 + ko + 64);
            #pragma unroll
            for (int ms = 0; ms < 4; ms++)
                #pragma unroll
                for (int ns = 0; ns < 4; ns++)
                    mma_bf16(acc[ms][ns], ah[ms], b2[ns]);
        }
        if (++st >= 3) st = 0;
    }

    if (O3) {
        const size_t ostr = (size_t)2 * N;
        #pragma unroll
        for (int ms = 0; ms < 4; ms++) {
            const size_t rr0 = arow0 + wm * 64 + ms * 16 + grp;
            #pragma unroll
            for (int ns = 0; ns < 4; ns++) {
                const size_t cc = bcol0 + wn * 32 + ns * 8 + tg * 2;
                float bx = bias[cc], by = bias[cc + 1];
                float v0 = fmaxf(acc[ms][ns][0] + bx, 0.f);
                float v1 = fmaxf(acc[ms][ns][1] + by, 0.f);
                float v2 = fmaxf(acc[ms][ns][2] + bx, 0.f);
                float v3 = fmaxf(acc[ms][ns][3] + by, 0.f);
                __nv_bfloat16* R0 = O3 + rr0 * ostr;
                __nv_bfloat16* R1 = O3 + (rr0 + 8) * ostr;
                *(uint32_t*)(R0 + cc)     = pack_hi2(v0, v1);
                *(uint32_t*)(R0 + N + cc) = pack_lo2(v0, v1);
                *(uint32_t*)(R1 + cc)     = pack_hi2(v2, v3);
                *(uint32_t*)(R1 + N + cc) = pack_lo2(v2, v3);
            }
        }
    } else {
        #pragma unroll
        for (int ms = 0; ms < 4; ms++) {
            const size_t rr0 = arow0 + wm * 64 + ms * 16 + grp;
            #pragma unroll
            for (int ns = 0; ns < 4; ns++) {
                const size_t cc = bcol0 + wn * 32 + ns * 8 + tg * 2;
                float bx = bias[cc], by = bias[cc + 1];
                float v0 = acc[ms][ns][0] + bx;
                float v1 = acc[ms][ns][1] + by;
                float v2 = acc[ms][ns][2] + bx;
                float v3 = acc[ms][ns][3] + by;
                if (relu) {
                    v0 = fmaxf(v0, 0.f); v1 = fmaxf(v1, 0.f);
                    v2 = fmaxf(v2, 0.f); v3 = fmaxf(v3, 0.f);
                }
                *(float2*)(C + rr0 * N + cc)       = make_float2(v0, v1);
                *(float2*)(C + (rr0 + 8) * N + cc) = make_float2(v2, v3);
            }
        }
    }
}

// ===================== attention scores + fused softmax stats ======
#define SPAD2 136
#define SCORES_SMEM ((128 + 64) * SPAD2 * 2 + 128 * 16 + 4096)
__global__ __launch_bounds__(256) void attn_scores_mma(
    const float* __restrict__ Q, int qstr,
    const float* __restrict__ Kv, int kstr,
    float* __restrict__ Sc, float* __restrict__ st,
    const int* __restrict__ mask, int causal)
{
    extern __shared__ __nv_bfloat16 sm[];
    __nv_bfloat16* As = sm;                 // [128][SPAD2]  Q: [hi|lo]
    __nv_bfloat16* Bs = sm + 128 * SPAD2;   // [64][SPAD2]   K: [hi|lo]
    float* stg = (float*)(sm + (128 + 64) * SPAD2);   // [128][2][2]
    int*   msk = (int*)(stg + 128 * 4);               // [1024]
    const int z = blockIdx.y, b = z >> 4, h = z & 15;
    const int q0 = blockIdx.x * 128;

    const int tid = threadIdx.x, lane = tid & 31, wid = tid >> 5;
    const int wm = wid >> 1, wn = wid & 1;
    const int grp = lane >> 2, tg = lane & 3;

    const float* Qb = Q + ((size_t)(b * TT + q0)) * qstr + h * DKD;

    #pragma unroll
    for (int i = 0; i < 8; i++) {
        int f = tid + i * 256;
        int r = f >> 4, c = (f & 15) << 2;
        float4 v = *(const float4*)(Qb + (size_t)r * qstr + c);
        uint2 hh, ll;
        hh.x = pack_hi2(v.x, v.y); hh.y = pack_hi2(v.z, v.w);
        ll.x = pack_lo2(v.x, v.y); ll.y = pack_lo2(v.z, v.w);
        __nv_bfloat16* R = As + r * SPAD2;
        *(uint2*)(R + c)      = hh;
        *(uint2*)(R + 64 + c) = ll;
    }
    if (!causal) {
        #pragma unroll
        for (int i = 0; i < 4; i++) msk[tid + i * 256] = mask[b * SS + tid + i * 256];
    }

    const uint32_t AsU = smem_u32(As), BsU = smem_u32(Bs);
    const uint32_t aLM = AsU + (uint32_t)(((wm * 32) + (lane & 15)) * SPAD2 + (lane >> 4) * 8) * 2;
    const uint32_t bLM = BsU + (uint32_t)(((wn * 32) + (lane & 15)) * SPAD2 + (lane >> 4) * 8) * 2;

    float ms_[2][2] = {{-3.0e38f, -3.0e38f}, {-3.0e38f, -3.0e38f}};
    float ss_[2][2] = {{0.f, 0.f}, {0.f, 0.f}};
    const int ktend = causal ? ((q0 >> 6) + 2) : 16;

    for (int kt = 0; kt < ktend; kt++) {
        const int k0 = kt * 64;
        __syncthreads();
        const float* Kb = Kv + ((size_t)(b * TT + k0)) * kstr + h * DKD;
        #pragma unroll
        for (int i = 0; i < 4; i++) {
            int f = tid + i * 256;
            int r = f >> 4, c = (f & 15) << 2;
            float4 v = *(const float4*)(Kb + (size_t)r * kstr + c);
            uint2 hh, ll;
            hh.x = pack_hi2(v.x, v.y); hh.y = pack_hi2(v.z, v.w);
            ll.x = pack_lo2(v.x, v.y); ll.y = pack_lo2(v.z, v.w);
            __nv_bfloat16* R = Bs + r * SPAD2;
            *(uint2*)(R + c)      = hh;
            *(uint2*)(R + 64 + c) = ll;
        }
        __syncthreads();

        float acc[2][4][4];
        #pragma unroll
        for (int i = 0; i < 2; i++)
            #pragma unroll
            for (int j = 0; j < 4; j++)
                #pragma unroll
                for (int q = 0; q < 4; q++) acc[i][j][q] = 0.f;

        #pragma unroll
        for (int ks = 0; ks < 4; ks++) {
            const uint32_t ko = ks * 32;
            uint32_t ah[2][4], al[2][4], bb[4][2];
            #pragma unroll
            for (int mi = 0; mi < 2; mi++)
                ldm4(ah[mi][0], ah[mi][1], ah[mi][2], ah[mi][3],
                     aLM + mi * (16 * SPAD2 * 2) + ko);
            ldm4(bb[0][0], bb[1][0], bb[0][1], bb[1][1], bLM + ko);
            ldm4(bb[2][0], bb[3][0], bb[2][1], bb[3][1], bLM + 16 * SPAD2 * 2 + ko);
            #pragma unroll
            for (int mi = 0; mi < 2; mi++)
                #pragma unroll
                for (int ni = 0; ni < 4; ni++)
                    mma_bf16(acc[mi][ni], ah[mi], bb[ni]);
            #pragma unroll
            for (int mi = 0; mi < 2; mi++)
                ldm4(al[mi][0], al[mi][1], al[mi][2], al[mi][3],
                     aLM + mi * (16 * SPAD2 * 2) + ko + 128);
            #pragma unroll
            for (int mi = 0; mi < 2; mi++)
                #pragma unroll
                for (int ni = 0; ni < 4; ni++)
                    mma_bf16(acc[mi][ni], al[mi], bb[ni]);
            ldm4(bb[0][0], bb[1][0], bb[0][1], bb[1][1], bLM + ko + 128);
            ldm4(bb[2][0], bb[3][0], bb[2][1], bb[3][1], bLM + 16 * SPAD2 * 2 + ko + 128);
            #pragma unroll
            for (int mi = 0; mi < 2; mi++)
                #pragma unroll
                for (int ni = 0; ni < 4; ni++)
                    mma_bf16(acc[mi][ni], ah[mi], bb[ni]);
        }

        float* Out = Sc + ((size_t)z * TT + q0) * TT + k0;
        #pragma unroll
        for (int mi = 0; mi < 2; mi++) {
            const size_t r = wm * 32 + mi * 16 + grp;
            #pragma unroll
            for (int ni = 0; ni < 4; ni++) {
                const size_t c = wn * 32 + ni * 8 + tg * 2;
                *(float2*)(Out + r * TT + c) =
                    make_float2(acc[mi][ni][0] * 0.125f, acc[mi][ni][1] * 0.125f);
                *(float2*)(Out + (r + 8) * TT + c) =
                    make_float2(acc[mi][ni][2] * 0.125f, acc[mi][ni][3] * 0.125f);
            }
        }
        #pragma unroll
        for (int mi = 0; mi < 2; mi++) {
            #pragma unroll
            for (int half = 0; half < 2; half++) {
                const int q = q0 + wm * 32 + mi * 16 + half * 8 + grp;
                float vv[8];
                float tm = -3.0e38f;
                #pragma unroll
                for (int ni = 0; ni < 4; ni++) {
                    #pragma unroll
                    for (int e = 0; e < 2; e++) {
                        int k = k0 + wn * 32 + ni * 8 + tg * 2 + e;
                        float v = acc[mi][ni][half * 2 + e] * 0.125f;
                        int valid = causal ? (k <= q) : msk[k];
                        v = valid ? v : -1e9f;
                        vv[ni * 2 + e] = v;
                        tm = fmaxf(tm, v);
                    }
                }
                float m = ms_[mi][half];
                float nm = fmaxf(m, tm);
                float as = 0.f;
                #pragma unroll
                for (int i = 0; i < 8; i++) as += __expf(vv[i] - nm);
                ss_[mi][half] = ss_[mi][half] * __expf(m - nm) + as;
                ms_[mi][half] = nm;
            }
        }
    }

    #pragma unroll
    for (int mi = 0; mi < 2; mi++) {
        #pragma unroll
        for (int half = 0; half < 2; half++) {
            float m = ms_[mi][half], s = ss_[mi][half];
            #pragma unroll
            for (int o = 1; o <= 2; o <<= 1) {
                float mo = __shfl_xor_sync(0xffffffffu, m, o);
                float so = __shfl_xor_sync(0xffffffffu, s, o);
                float nm = fmaxf(m, mo);
                s = s * __expf(m - nm) + so * __expf(mo - nm);
                m = nm;
            }
            if (tg == 0) {
                int row = wm * 32 + mi * 16 + half * 8 + grp;
                stg[(row * 2 + wn) * 2]     = m;
                stg[(row * 2 + wn) * 2 + 1] = s;
            }
        }
    }
    __syncthreads();
    if (tid < 128) {
        float m0 = stg[(tid * 2) * 2],     s0 = stg[(tid * 2) * 2 + 1];
        float m1 = stg[(tid * 2 + 1) * 2], s1 = stg[(tid * 2 + 1) * 2 + 1];
        float M = fmaxf(m0, m1);
        float S = s0 * __expf(m0 - M) + s1 * __expf(m1 - M);
        st[((size_t)z * TT + q0 + tid) * 2]     = M;
        st[((size_t)z * TT + q0 + tid) * 2 + 1] = 1.0f / S;
    }
}

// ===================== attn @ V with fused softmax-apply =====================
#define AV_SMEM ((64 + 64) * SPAD2 * 2 + 512)
__global__ __launch_bounds__(256) void attn_av_mma(
    float* __restrict__ Sc, const __nv_bfloat16* __restrict__ VT2,
    const float* __restrict__ st, const int* __restrict__ mask,
    __nv_bfloat16* __restrict__ A2out, int causal)
{
    extern __shared__ __nv_bfloat16 sm[];
    __nv_bfloat16* As = sm;                // [64][SPAD2]  P: [hi|lo]
    __nv_bfloat16* Bs = sm + 64 * SPAD2;   // [64][SPAD2]  V^T: [hi|lo]
    float* stats = (float*)(sm + (64 + 64) * SPAD2);
    const int z = blockIdx.y, b = z >> 4, h = z & 15;
    const int q0 = blockIdx.x * 64;

    const int tid = threadIdx.x, lane = tid & 31, wid = tid >> 5;
    const int wm = wid >> 1, wn = wid & 1;
    const int grp = lane >> 2, tg = lane & 3;

    const int kend = causal ? (q0 + 64) : TT;

    if (tid < 64) {
        stats[tid]      = st[((size_t)z * TT + q0 + tid) * 2];
        stats[64 + tid] = st[((size_t)z * TT + q0 + tid) * 2 + 1];
    }
    __syncthreads();

    const __nv_bfloat16* Vt = VT2 + (size_t)z * 64 * 2048;
    const uint32_t AsU = smem_u32(As), BsU = smem_u32(Bs);
    const uint32_t aLM = AsU + (uint32_t)(((wm * 16) + (lane & 15)) * SPAD2 + (lane >> 4) * 8) * 2;
    const uint32_t bLM = BsU + (uint32_t)(((wn * 32) + (lane & 15)) * SPAD2 + (lane >> 4) * 8) * 2;

    float acc[4][4];
    #pragma unroll
    for (int i = 0; i < 4; i++)
        #pragma unroll
        for (int j = 0; j < 4; j++) acc[i][j] = 0.f;

    for (int k0 = 0; k0 < kend; k0 += 64) {
        float* Pb = Sc + ((size_t)z * TT + q0) * TT + k0;
        #pragma unroll
        for (int i = 0; i < 4; i++) {
            int f = tid + i * 256;
            int r = f >> 4, c = (f & 15) << 2;
            float4 pv = *(float4*)(Pb + (size_t)r * TT + c);
            const int qabs = q0 + r;
            const int kg = k0 + c;
            float v0, v1, v2, v3;
            if (causal) {
                v0 = (kg     <= qabs) ? pv.x : -1e9f;
                v1 = (kg + 1 <= qabs) ? pv.y : -1e9f;
                v2 = (kg + 2 <= qabs) ? pv.z : -1e9f;
                v3 = (kg + 3 <= qabs) ? pv.w : -1e9f;
            } else {
                int4 mk = *(const int4*)(mask + b * SS + kg);
                v0 = mk.x ? pv.x : -1e9f;
                v1 = mk.y ? pv.y : -1e9f;
                v2 = mk.z ? pv.z : -1e9f;
                v3 = mk.w ? pv.w : -1e9f;
            }
            const float mm = stats[r], iv = stats[64 + r];
            float p0 = __expf(v0 - mm) * iv;
            float p1 = __expf(v1 - mm) * iv;
            float p2 = __expf(v2 - mm) * iv;
            float p3 = __expf(v3 - mm) * iv;
            *(float4*)(Pb + (size_t)r * TT + c) = make_float4(p0, p1, p2, p3);
            uint2 hh, ll;
            hh.x = pack_hi2(p0, p1); hh.y = pack_hi2(p2, p3);
            ll.x = pack_lo2(p0, p1); ll.y = pack_lo2(p2, p3);
            __nv_bfloat16* R = As + r * SPAD2;
            *(uint2*)(R + c)      = hh;
            *(uint2*)(R + 64 + c) = ll;
        }
        #pragma unroll
        for (int i = 0; i < 4; i++) {
            int idx = tid + i * 256;
            int d = idx >> 4, rem = idx & 15;
            int band = rem >> 3, j = rem & 7;
            uint4 v = *(const uint4*)(Vt + (size_t)d * 2048 + band * 1024 + k0 + j * 8);
            *(uint4*)(Bs + d * SPAD2 + band * 64 + j * 8) = v;
        }
        __syncthreads();
        #pragma unroll
        for (int ks = 0; ks < 4; ks++) {
            const uint32_t ko = ks * 32;
            uint32_t ah[4], al[4], bb[4][2];
            ldm4(ah[0], ah[1], ah[2], ah[3], aLM + ko);
            ldm4(bb[0][0], bb[1][0], bb[0][1], bb[1][1], bLM + ko);
            ldm4(bb[2][0], bb[3][0], bb[2][1], bb[3][1], bLM + 16 * SPAD2 * 2 + ko);
            #pragma unroll
            for (int ni = 0; ni < 4; ni++)
                mma_bf16(acc[ni], ah, bb[ni]);
            ldm4(al[0], al[1], al[2], al[3], aLM + ko + 128);
            #pragma unroll
            for (int ni = 0; ni < 4; ni++)
                mma_bf16(acc[ni], al, bb[ni]);
            ldm4(bb[0][0], bb[1][0], bb[0][1], bb[1][1], bLM + ko + 128);
            ldm4(bb[2][0], bb[3][0], bb[2][1], bb[3][1], bLM + 16 * SPAD2 * 2 + ko + 128);
            #pragma unroll
            for (int ni = 0; ni < 4; ni++)
                mma_bf16(acc[ni], ah, bb[ni]);
        }
        __syncthreads();
    }

    if (causal && kend < TT) {
        const int Z = TT - kend;
        const int zw = Z >> 2;
        const int n4 = 64 * zw;
        const float4 z4 = make_float4(0.f, 0.f, 0.f, 0.f);
        for (int i = tid; i < n4; i += 256) {
            int r = i / zw, c = kend + (i - r * zw) * 4;
            *(float4*)(Sc + ((size_t)z * TT + q0 + r) * TT + c) = z4;
        }
    }

    const size_t m0 = (size_t)b * TT + q0 + wm * 16 + grp;
    const size_t m1 = m0 + 8;
    __nv_bfloat16* R0 = A2out + m0 * 2048;
    __nv_bfloat16* R1 = A2out + m1 * 2048;
    #pragma unroll
    for (int ni = 0; ni < 4; ni++) {
        const int cc = h * DKD + wn * 32 + ni * 8 + tg * 2;
        float v0 = acc[ni][0], v1 = acc[ni][1];
        float v2 = acc[ni][2], v3 = acc[ni][3];
        *(uint32_t*)(R0 + cc)        = pack_hi2(v0, v1);
        *(uint32_t*)(R0 + 1024 + cc) = pack_lo2(v0, v1);
        *(uint32_t*)(R1 + cc)        = pack_hi2(v2, v3);
        *(uint32_t*)(R1 + 1024 + cc) = pack_lo2(v2, v3);
    }
}

// ===================== residual add + LayerNorm =====================
__global__ __launch_bounds__(256) void add_ln(
    const float* __restrict__ X, const float* __restrict__ Dl,
    const float* __restrict__ g, const float* __restrict__ be,
    float* __restrict__ O, __nv_bfloat16* __restrict__ S2)
{
    const int row = blockIdx.x;
    const float* x  = X  + (size_t)row * DD;
    const float* dl = Dl + (size_t)row * DD;
    const int tid = threadIdx.x;

    float v[4];
    float s = 0.f;
    #pragma unroll
    for (int i = 0; i < 4; i++) {
        int c = tid + i * 256;
        v[i] = x[c] + dl[c];
        s += v[i];
    }
    __shared__ float red[8];
    #pragma unroll
    for (int o = 16; o > 0; o >>= 1) s += __shfl_xor_sync(0xffffffffu, s, o);
    if ((tid & 31) == 0) red[tid >> 5] = s;
    __syncthreads();
    s = 0.f;
    #pragma unroll
    for (int w = 0; w < 8; w++) s += red[w];
    float mean = s * (1.0f / 1024.0f);

    float qq = 0.f;
    #pragma unroll
    for (int i = 0; i < 4; i++) { float d = v[i] - mean; qq += d * d; }
    __syncthreads();
    #pragma unroll
    for (int o = 16; o > 0; o >>= 1) qq += __shfl_xor_sync(0xffffffffu, qq, o);
    if ((tid & 31) == 0) red[tid >> 5] = qq;
    __syncthreads();
    qq = 0.f;
    #pragma unroll
    for (int w = 0; w < 8; w++) qq += red[w];

    float stdv = sqrtf(qq * (1.0f / 1023.0f));
    float inv = 1.0f / (stdv + LN_EPS);
    __nv_bfloat16* R = S2 ? (S2 + (size_t)row * 2048) : (__nv_bfloat16*)0;
    #pragma unroll
    for (int i = 0; i < 4; i++) {
        int c = tid + i * 256;
        float o = g[c] * (v[i] - mean) * inv + be[c];
        O[(size_t)row * DD + c] = o;
        if (R) {
            __nv_bfloat16 h = __float2bfloat16(o);
            __nv_bfloat16 l = __float2bfloat16(o - __bfloat162float(h));
            R[c]        = h;
            R[1024 + c] = l;
        }
    }
}

// ===================== orchestration =====================
extern "C" void kernel_launch(void* const* d_in, const int* in_sizes, int n_in,
                              void* d_out, int out_size)
{
    const float* x        = (const float*)d_in[0];
    const float* enc      = (const float*)d_in[1];
    const int*   src_mask = (const int*)  d_in[2];
    const float* wq_s = (const float*)d_in[4],  *bq_s = (const float*)d_in[5];
    const float* wk_s = (const float*)d_in[6],  *bk_s = (const float*)d_in[7];
    const float* wv_s = (const float*)d_in[8],  *bv_s = (const float*)d_in[9];
    const float* wo_s = (const float*)d_in[10], *bo_s = (const float*)d_in[11];
    const float* wq_c = (const float*)d_in[12], *bq_c = (const float*)d_in[13];
    const float* wk_c = (const float*)d_in[14], *bk_c = (const float*)d_in[15];
    const float* wv_c = (const float*)d_in[16], *bv_c = (const float*)d_in[17];
    const float* w1   = (const float*)d_in[20], *b1   = (const float*)d_in[21];
    const float* w2   = (const float*)d_in[22], *b2   = (const float*)d_in[23];
    const float* g1   = (const float*)d_in[24], *be1  = (const float*)d_in[25];
    const float* g2   = (const float*)d_in[26], *be2  = (const float*)d_in[27];
    const float* g3   = (const float*)d_in[28], *be3  = (const float*)d_in[29];
    const float* bo_c2 = (const float*)d_in[19];

    float* out     = (float*)d_out;
    float* self_w  = out + (size_t)BB * TT * DD;
    float* cross_w = self_w + (size_t)BB * HH * TT * TT;

    float *QKV, *T1, *X1, *X2, *ST, *BS, *BC;
    __nv_bfloat16 *A2, *FF2, *WT2, *VT2;
    cudaGetSymbolAddress((void**)&QKV, g_qkv);
    cudaGetSymbolAddress((void**)&T1,  g_t1);
    cudaGetSymbolAddress((void**)&X1,  g_x1);
    cudaGetSymbolAddress((void**)&X2,  g_x2);
    cudaGetSymbolAddress((void**)&ST,  g_st);
    cudaGetSymbolAddress((void**)&BS,  g_bs);
    cudaGetSymbolAddress((void**)&BC,  g_bc);
    cudaGetSymbolAddress((void**)&A2,  g_a2);
    cudaGetSymbolAddress((void**)&FF2, g_ff2);
    cudaGetSymbolAddress((void**)&WT2, g_wt2);
    cudaGetSymbolAddress((void**)&VT2, g_vt2);

    cudaFuncSetAttribute(gemm_mma,        cudaFuncAttributeMaxDynamicSharedMemorySize, GEMM_SMEM);
    cudaFuncSetAttribute(attn_scores_mma, cudaFuncAttributeMaxDynamicSharedMemorySize, SCORES_SMEM);
    cudaFuncSetAttribute(attn_av_mma,     cudaFuncAttributeMaxDynamicSharedMemorySize, AV_SMEM);

    const int M = BB * TT;
    dim3 blk(256);
    dim3 tp32(32, 32);
    dim3 gD(DD / 128, M / 128);
    dim3 gQKV(3072 / 128, M / 128);
    dim3 gKV(2048 / 128, M / 128);
    dim3 gF(DFFN / 128, M / 128);
    dim3 scoreG(TT / 128, BB * HH);
    dim3 avG(TT / 64, BB * HH);
    dim3 vtG(TT / 32, DD / 32, BB);
    dim3 lnG(M);
    const int ACT_BLKS = M * DD / 4 / 256;
    float* NC = (float*)0;
    __nv_bfloat16* NO3 = (__nv_bfloat16*)0;
    float* QKV2 = QKV + (size_t)M * 1024;   // cross KV region

    // ---- concat biases (graph-legal D2D copies) ----
    cudaMemcpyAsync(BS,        bq_s, 1024 * 4, cudaMemcpyDeviceToDevice);
    cudaMemcpyAsync(BS + 1024, bk_s, 1024 * 4, cudaMemcpyDeviceToDevice);
    cudaMemcpyAsync(BS + 2048, bv_s, 1024 * 4, cudaMemcpyDeviceToDevice);
    cudaMemcpyAsync(BC,        bk_c, 1024 * 4, cudaMemcpyDeviceToDevice);
    cudaMemcpyAsync(BC + 1024, bv_c, 1024 * 4, cudaMemcpyDeviceToDevice);

    // ---- self attention ----
    split_act<<<ACT_BLKS, blk>>>(x, A2);
    split_w<<<dim3(32, 32), tp32>>>(wq_s, WT2 + 0 * W2D, DD, DD);
    split_w<<<dim3(32, 32), tp32>>>(wk_s, WT2 + 1 * W2D, DD, DD);
    split_w<<<dim3(32, 32), tp32>>>(wv_s, WT2 + 2 * W2D, DD, DD);
    split_w<<<dim3(32, 32), tp32>>>(wo_s, WT2 + 3 * W2D, DD, DD);
    gemm_mma<<<gQKV, blk, GEMM_SMEM>>>(A2, WT2 + 0 * W2D, BS, QKV, NO3, 3072, 1024, 0);
    vt_split<<<vtG, tp32>>>(QKV + 2048, 3072, VT2);
    attn_scores_mma<<<scoreG, blk, SCORES_SMEM>>>(QKV, 3072, QKV + 1024, 3072,
                                                  self_w, ST, src_mask, 1);
    attn_av_mma<<<avG, blk, AV_SMEM>>>(self_w, VT2, ST, src_mask, A2, 1);
    gemm_mma<<<gD, blk, GEMM_SMEM>>>(A2, WT2 + 3 * W2D, bo_s, T1, NO3, DD, 1024, 0);
    add_ln<<<lnG, blk>>>(x, T1, g1, be1, X1, A2);

    // ---- remaining weight splits ----
    split_w<<<dim3(32, 32), tp32>>>(wq_c, WT2 + 4 * W2D, DD, DD);
    split_w<<<dim3(32, 32), tp32>>>(wk_c, WT2 + 5 * W2D, DD, DD);
    split_w<<<dim3(32, 32), tp32>>>(wv_c, WT2 + 6 * W2D, DD, DD);
    split_w<<<dim3(32, 32), tp32>>>((const float*)d_in[18], WT2 + 7 * W2D, DD, DD);
    split_w<<<dim3(128, 32), tp32>>>(w1, WT2 + W1OFF, DD, DFFN);
    split_w<<<dim3(32, 128), tp32>>>(w2, WT2 + W2OFF, DFFN, DD);

    // ---- cross attention ----
    gemm_mma<<<gD, blk, GEMM_SMEM>>>(A2, WT2 + 4 * W2D, bq_c, QKV, NO3, DD, 1024, 0);
    split_act<<<ACT_BLKS, blk>>>(enc, A2);
    gemm_mma<<<gKV, blk, GEMM_SMEM>>>(A2, WT2 + 5 * W2D, BC, QKV2, NO3, 2048, 1024, 0);
    vt_split<<<vtG, tp32>>>(QKV2 + 1024, 2048, VT2);
    attn_scores_mma<<<scoreG, blk, SCORES_SMEM>>>(QKV, 1024, QKV2, 2048,
                                                  cross_w, ST, src_mask, 0);
    attn_av_mma<<<avG, blk, AV_SMEM>>>(cross_w, VT2, ST, src_mask, A2, 0);
    gemm_mma<<<gD, blk, GEMM_SMEM>>>(A2, WT2 + 7 * W2D, bo_c2, T1, NO3, DD, 1024, 0);
    add_ln<<<lnG, blk>>>(X1, T1, g2, be2, X2, A2);

    // ---- feed-forward ----
    gemm_mma<<<gF, blk, GEMM_SMEM>>>(A2, WT2 + W1OFF, b1, NC, FF2, DFFN, 1024, 1);
    gemm_mma<<<gD, blk, GEMM_SMEM>>>(FF2, WT2 + W2OFF, b2, T1, NO3, DD, 4096, 0);
    add_ln<<<lnG, blk>>>(X2, T1, g3, be3, out, NO3);

    (void)in_sizes; (void)n_in; (void)out_size; (void)bv_c;
}

// round 16
// speedup vs baseline: 1.0621x; 1.0259x over previous
#include <cuda_runtime.h>
#include <cuda_bf16.h>
#include <math.h>
#include <stdint.h>

#define BB 4
#define TT 1024
#define SS 1024
#define DD 1024
#define HH 16
#define DKD 64
#define DFFN 4096
#define LN_EPS 1e-6f

// ===================== scratch (no allocations) =====================
__device__ float g_qkv[4096ULL * 3072];           // fused QKV (self) / Q + KV (cross)
__device__ float g_t1[BB*TT*DD];
__device__ float g_x1[BB*TT*DD];
__device__ float g_x2[BB*TT*DD];
__device__ float g_st[64ULL * 1024 * 2];          // per (z,q): max, inv_sum
__device__ float g_bs[3072];                      // concat bias self QKV
__device__ float g_bc[2048];                      // concat bias cross KV

__device__ __nv_bfloat16 g_a2 [4096ULL * 2048];   // activations [M,2K] (hi|lo)
__device__ __nv_bfloat16 g_ff2[4096ULL * 8192];   // FF activations (hi|lo)
__device__ __nv_bfloat16 g_vt2[4096ULL * 2048];   // V^T split per (b,h): [64 d][hi|lo seq]
#define W2D (1024ULL*2048)
#define W1OFF (8*W2D)
#define W2OFF (8*W2D + 4096ULL*2048)
__device__ __nv_bfloat16 g_wt2[8*W2D + 4096ULL*2048 + 1024ULL*8192];

// ===================== helpers =====================
__device__ __forceinline__ uint32_t pack_hi2(float x, float y) {
    __nv_bfloat16 a = __float2bfloat16(x), b = __float2bfloat16(y);
    return (uint32_t)__bfloat16_as_ushort(a) | ((uint32_t)__bfloat16_as_ushort(b) << 16);
}
__device__ __forceinline__ uint32_t pack_lo2(float x, float y) {
    __nv_bfloat16 a = __float2bfloat16(x), b = __float2bfloat16(y);
    __nv_bfloat16 ra = __float2bfloat16(x - __bfloat162float(a));
    __nv_bfloat16 rb = __float2bfloat16(y - __bfloat162float(b));
    return (uint32_t)__bfloat16_as_ushort(ra) | ((uint32_t)__bfloat16_as_ushort(rb) << 16);
}
__device__ __forceinline__ void mma_bf16(
    float* d, const uint32_t* a, const uint32_t* b)
{
    asm volatile(
        "mma.sync.aligned.m16n8k16.row.col.f32.bf16.bf16.f32 "
        "{%0,%1,%2,%3}, {%4,%5,%6,%7}, {%8,%9}, {%0,%1,%2,%3};"
        : "+f"(d[0]), "+f"(d[1]), "+f"(d[2]), "+f"(d[3])
        : "r"(a[0]), "r"(a[1]), "r"(a[2]), "r"(a[3]), "r"(b[0]), "r"(b[1]));
}
__device__ __forceinline__ uint32_t smem_u32(const void* p) {
    uint32_t a;
    asm("{ .reg .u64 t; cvta.to.shared.u64 t, %1; cvt.u32.u64 %0, t; }" : "=r"(a) : "l"(p));
    return a;
}
__device__ __forceinline__ void cp16(uint32_t s, const void* g) {
    asm volatile("cp.async.cg.shared.global [%0], [%1], 16;" :: "r"(s), "l"(g));
}
#define CP_COMMIT() asm volatile("cp.async.commit_group;" ::: "memory")
#define CP_WAIT1()  asm volatile("cp.async.wait_group 1;" ::: "memory")
__device__ __forceinline__ void ldm4(uint32_t& r0, uint32_t& r1, uint32_t& r2, uint32_t& r3, uint32_t a) {
    asm volatile("ldmatrix.sync.aligned.m8n8.x4.shared.b16 {%0,%1,%2,%3}, [%4];"
        : "=r"(r0), "=r"(r1), "=r"(r2), "=r"(r3) : "r"(a));
}

// ===================== split/convert kernels =====================
__global__ __launch_bounds__(256) void split_act(
    const float* __restrict__ A, __nv_bfloat16* __restrict__ O)
{
    const int K = 1024;
    size_t idx = (size_t)blockIdx.x * 256 + threadIdx.x;
    size_t base = idx << 2;
    size_t m = base >> 10;
    int k = (int)(base & (size_t)(K - 1));
    float4 v = *(const float4*)(A + base);
    uint2 hh, ll;
    hh.x = pack_hi2(v.x, v.y); hh.y = pack_hi2(v.z, v.w);
    ll.x = pack_lo2(v.x, v.y); ll.y = pack_lo2(v.z, v.w);
    __nv_bfloat16* row = O + m * (size_t)(2 * K);
    *(uint2*)(row + k)     = hh;
    *(uint2*)(row + K + k) = ll;
}

// W [K, N] fp32 -> O [N, 2K] bf16 (hi|lo), vectorized transpose.
// Tile 32 k x 128 n, 256 threads. Grid (N/128, K/32).
__global__ __launch_bounds__(256) void split_w(
    const float* __restrict__ W, __nv_bfloat16* __restrict__ O, int K, int N)
{
    __shared__ float t[32][133];
    const int k0 = blockIdx.y * 32;
    const int n0 = blockIdx.x * 128;
    const int tid = threadIdx.x;

    #pragma unroll
    for (int i = 0; i < 4; i++) {
        int idx = tid + i * 256;
        int row = idx >> 5, c4 = (idx & 31) << 2;
        float4 v = *(const float4*)(W + (size_t)(k0 + row) * N + n0 + c4);
        t[row][c4] = v.x; t[row][c4 + 1] = v.y;
        t[row][c4 + 2] = v.z; t[row][c4 + 3] = v.w;
    }
    __syncthreads();

    #pragma unroll
    for (int i = 0; i < 4; i++) {
        int idx = tid + i * 256;
        int nn = idx >> 3, kg = (idx & 7) << 2;
        float v0 = t[kg][nn], v1 = t[kg + 1][nn];
        float v2 = t[kg + 2][nn], v3 = t[kg + 3][nn];
        uint2 hh, ll;
        hh.x = pack_hi2(v0, v1); hh.y = pack_hi2(v2, v3);
        ll.x = pack_lo2(v0, v1); ll.y = pack_lo2(v2, v3);
        size_t ro = (size_t)(n0 + nn) * (size_t)(2 * K) + k0 + kg;
        *(uint2*)(O + ro)     = hh;
        *(uint2*)(O + ro + K) = ll;
    }
}

// V rows (stride vstr) -> VT2 per (b,h): [64 d][hi|lo seq], vectorized.
// Tile 32 k x 128 d, 256 threads. Grid (TT/32, DD/128, BB).
__global__ __launch_bounds__(256) void vt_split(
    const float* __restrict__ V, int vstr, __nv_bfloat16* __restrict__ VT2)
{
    __shared__ float t[32][133];
    const int b = blockIdx.z;
    const int k0 = blockIdx.x * 32;
    const int d0 = blockIdx.y * 128;
    const int tid = threadIdx.x;

    #pragma unroll
    for (int i = 0; i < 4; i++) {
        int idx = tid + i * 256;
        int row = idx >> 5, c4 = (idx & 31) << 2;
        float4 v = *(const float4*)(V + (size_t)(b * TT + k0 + row) * vstr + d0 + c4);
        t[row][c4] = v.x; t[row][c4 + 1] = v.y;
        t[row][c4 + 2] = v.z; t[row][c4 + 3] = v.w;
    }
    __syncthreads();

    #pragma unroll
    for (int i = 0; i < 4; i++) {
        int idx = tid + i * 256;
        int dd = idx >> 3, kg = (idx & 7) << 2;
        int dg = d0 + dd;
        int hh_ = dg >> 6, dk = dg & 63;
        size_t row = ((size_t)(b * HH + hh_) * 64 + dk) * 2048;
        float v0 = t[kg][dd], v1 = t[kg + 1][dd];
        float v2 = t[kg + 2][dd], v3 = t[kg + 3][dd];
        uint2 hh, ll;
        hh.x = pack_hi2(v0, v1); hh.y = pack_hi2(v2, v3);
        ll.x = pack_lo2(v0, v1); ll.y = pack_lo2(v2, v3);
        *(uint2*)(VT2 + row + k0 + kg)        = hh;
        *(uint2*)(VT2 + row + 1024 + k0 + kg) = ll;
    }
}

// ===================== HMMA GEMM, 2-segment operands, 3 products in-smem ====
#define PADK2 72
#define TSTG (128 * PADK2 * 2)
#define SSTG (2 * TSTG)
#define STAGES2 3
#define GEMM_SMEM (STAGES2 * SSTG)

__global__ __launch_bounds__(256) void gemm_mma(
    const __nv_bfloat16* __restrict__ A2, const __nv_bfloat16* __restrict__ W2,
    const float* __restrict__ bias, float* __restrict__ C,
    __nv_bfloat16* __restrict__ O3, int N, int Kl, int relu)
{
    extern __shared__ char dsm[];
    const uint32_t sb = smem_u32(dsm);
    const int tid = threadIdx.x;
    const int lane = tid & 31, wid = tid >> 5;
    const int wm = wid >> 2, wn = wid & 3;
    const int grp = lane >> 2, tg = lane & 3;

    const size_t arow0 = (size_t)blockIdx.y * 128;
    const size_t bcol0 = (size_t)blockIdx.x * 128;
    const size_t rstr = (size_t)2 * Kl;

    const uint32_t aLM = (uint32_t)(((wm * 64) + (lane & 15)) * PADK2 + (lane >> 4) * 8) * 2;
    const uint32_t bLM = (uint32_t)(((wn * 32) + (lane & 15)) * PADK2 + (lane >> 4) * 8) * 2;

    float acc[4][4][4];
    #pragma unroll
    for (int i = 0; i < 4; i++)
        #pragma unroll
        for (int j = 0; j < 4; j++)
            #pragma unroll
            for (int q = 0; q < 4; q++) acc[i][j][q] = 0.f;

    const int NC = Kl >> 5;

    auto issue = [&](int c, int st) {
        const uint32_t ab = sb + st * SSTG;
        const uint32_t bb = ab + TSTG;
        #pragma unroll
        for (int i = 0; i < 4; i++) {
            int idx = tid + i * 256;
            int r = idx >> 3, s = idx & 7;
            size_t go = (s < 4) ? ((size_t)c * 32 + s * 8)
                                : ((size_t)Kl + c * 32 + (s - 4) * 8);
            uint32_t so = (uint32_t)(r * PADK2 + s * 8) * 2;
            cp16(ab + so, A2 + (arow0 + r) * rstr + go);
            cp16(bb + so, W2 + (bcol0 + r) * rstr + go);
        }
        CP_COMMIT();
    };

    issue(0, 0); issue(1, 1);

    int st = 0;
    for (int c = 0; c < NC; c++) {
        CP_WAIT1();
        __syncthreads();
        if (c + 2 < NC) {
            int ns = st + 2; if (ns >= 3) ns -= 3;
            issue(c + 2, ns);
        } else CP_COMMIT();

        const uint32_t As0 = sb + st * SSTG;
        const uint32_t Bs0 = As0 + TSTG;
        #pragma unroll
        for (int ks = 0; ks < 2; ks++) {
            const uint32_t ko = ks * 32;
            uint32_t ah[4][4], al[4][4], b2[4][2];
            #pragma unroll
            for (int ms = 0; ms < 4; ms++)
                ldm4(ah[ms][0], ah[ms][1], ah[ms][2], ah[ms][3],
                     As0 + aLM + ms * (16 * PADK2 * 2) + ko);
            ldm4(b2[0][0], b2[1][0], b2[0][1], b2[1][1], Bs0 + bLM + ko);
            ldm4(b2[2][0], b2[3][0], b2[2][1], b2[3][1], Bs0 + bLM + 16 * PADK2 * 2 + ko);
            #pragma unroll
            for (int ms = 0; ms < 4; ms++)
                #pragma unroll
                for (int ns = 0; ns < 4; ns++)
                    mma_bf16(acc[ms][ns], ah[ms], b2[ns]);
            #pragma unroll
            for (int ms = 0; ms < 4; ms++)
                ldm4(al[ms][0], al[ms][1], al[ms][2], al[ms][3],
                     As0 + aLM + ms * (16 * PADK2 * 2) + ko + 64);
            #pragma unroll
            for (int ms = 0; ms < 4; ms++)
                #pragma unroll
                for (int ns = 0; ns < 4; ns++)
                    mma_bf16(acc[ms][ns], al[ms], b2[ns]);
            ldm4(b2[0][0], b2[1][0], b2[0][1], b2[1][1], Bs0 + bLM + ko + 64);
            ldm4(b2[2][0], b2[3][0], b2[2][1], b2[3][1], Bs0 + bLM + 16 * PADK2 * 2 + ko + 64);
            #pragma unroll
            for (int ms = 0; ms < 4; ms++)
                #pragma unroll
                for (int ns = 0; ns < 4; ns++)
                    mma_bf16(acc[ms][ns], ah[ms], b2[ns]);
        }
        if (++st >= 3) st = 0;
    }

    if (O3) {
        const size_t ostr = (size_t)2 * N;
        #pragma unroll
        for (int ms = 0; ms < 4; ms++) {
            const size_t rr0 = arow0 + wm * 64 + ms * 16 + grp;
            #pragma unroll
            for (int ns = 0; ns < 4; ns++) {
                const size_t cc = bcol0 + wn * 32 + ns * 8 + tg * 2;
                float bx = bias[cc], by = bias[cc + 1];
                float v0 = fmaxf(acc[ms][ns][0] + bx, 0.f);
                float v1 = fmaxf(acc[ms][ns][1] + by, 0.f);
                float v2 = fmaxf(acc[ms][ns][2] + bx, 0.f);
                float v3 = fmaxf(acc[ms][ns][3] + by, 0.f);
                __nv_bfloat16* R0 = O3 + rr0 * ostr;
                __nv_bfloat16* R1 = O3 + (rr0 + 8) * ostr;
                *(uint32_t*)(R0 + cc)     = pack_hi2(v0, v1);
                *(uint32_t*)(R0 + N + cc) = pack_lo2(v0, v1);
                *(uint32_t*)(R1 + cc)     = pack_hi2(v2, v3);
                *(uint32_t*)(R1 + N + cc) = pack_lo2(v2, v3);
            }
        }
    } else {
        #pragma unroll
        for (int ms = 0; ms < 4; ms++) {
            const size_t rr0 = arow0 + wm * 64 + ms * 16 + grp;
            #pragma unroll
            for (int ns = 0; ns < 4; ns++) {
                const size_t cc = bcol0 + wn * 32 + ns * 8 + tg * 2;
                float bx = bias[cc], by = bias[cc + 1];
                float v0 = acc[ms][ns][0] + bx;
                float v1 = acc[ms][ns][1] + by;
                float v2 = acc[ms][ns][2] + bx;
                float v3 = acc[ms][ns][3] + by;
                if (relu) {
                    v0 = fmaxf(v0, 0.f); v1 = fmaxf(v1, 0.f);
                    v2 = fmaxf(v2, 0.f); v3 = fmaxf(v3, 0.f);
                }
                *(float2*)(C + rr0 * N + cc)       = make_float2(v0, v1);
                *(float2*)(C + (rr0 + 8) * N + cc) = make_float2(v2, v3);
            }
        }
    }
}

// ===================== attention scores + fused softmax stats ======
#define SPAD2 136
#define SCORES_SMEM ((128 + 64) * SPAD2 * 2 + 128 * 16 + 4096)
__global__ __launch_bounds__(256) void attn_scores_mma(
    const float* __restrict__ Q, int qstr,
    const float* __restrict__ Kv, int kstr,
    float* __restrict__ Sc, float* __restrict__ st,
    const int* __restrict__ mask, int causal)
{
    extern __shared__ __nv_bfloat16 sm[];
    __nv_bfloat16* As = sm;                 // [128][SPAD2]  Q: [hi|lo]
    __nv_bfloat16* Bs = sm + 128 * SPAD2;   // [64][SPAD2]   K: [hi|lo]
    float* stg = (float*)(sm + (128 + 64) * SPAD2);   // [128][2][2]
    int*   msk = (int*)(stg + 128 * 4);               // [1024]
    const int z = blockIdx.y, b = z >> 4, h = z & 15;
    const int q0 = blockIdx.x * 128;

    const int tid = threadIdx.x, lane = tid & 31, wid = tid >> 5;
    const int wm = wid >> 1, wn = wid & 1;
    const int grp = lane >> 2, tg = lane & 3;

    const float* Qb = Q + ((size_t)(b * TT + q0)) * qstr + h * DKD;

    #pragma unroll
    for (int i = 0; i < 8; i++) {
        int f = tid + i * 256;
        int r = f >> 4, c = (f & 15) << 2;
        float4 v = *(const float4*)(Qb + (size_t)r * qstr + c);
        uint2 hh, ll;
        hh.x = pack_hi2(v.x, v.y); hh.y = pack_hi2(v.z, v.w);
        ll.x = pack_lo2(v.x, v.y); ll.y = pack_lo2(v.z, v.w);
        __nv_bfloat16* R = As + r * SPAD2;
        *(uint2*)(R + c)      = hh;
        *(uint2*)(R + 64 + c) = ll;
    }
    if (!causal) {
        #pragma unroll
        for (int i = 0; i < 4; i++) msk[tid + i * 256] = mask[b * SS + tid + i * 256];
    }

    const uint32_t AsU = smem_u32(As), BsU = smem_u32(Bs);
    const uint32_t aLM = AsU + (uint32_t)(((wm * 32) + (lane & 15)) * SPAD2 + (lane >> 4) * 8) * 2;
    const uint32_t bLM = BsU + (uint32_t)(((wn * 32) + (lane & 15)) * SPAD2 + (lane >> 4) * 8) * 2;

    float ms_[2][2] = {{-3.0e38f, -3.0e38f}, {-3.0e38f, -3.0e38f}};
    float ss_[2][2] = {{0.f, 0.f}, {0.f, 0.f}};
    const int ktend = causal ? ((q0 >> 6) + 2) : 16;

    for (int kt = 0; kt < ktend; kt++) {
        const int k0 = kt * 64;
        __syncthreads();
        const float* Kb = Kv + ((size_t)(b * TT + k0)) * kstr + h * DKD;
        #pragma unroll
        for (int i = 0; i < 4; i++) {
            int f = tid + i * 256;
            int r = f >> 4, c = (f & 15) << 2;
            float4 v = *(const float4*)(Kb + (size_t)r * kstr + c);
            uint2 hh, ll;
            hh.x = pack_hi2(v.x, v.y); hh.y = pack_hi2(v.z, v.w);
            ll.x = pack_lo2(v.x, v.y); ll.y = pack_lo2(v.z, v.w);
            __nv_bfloat16* R = Bs + r * SPAD2;
            *(uint2*)(R + c)      = hh;
            *(uint2*)(R + 64 + c) = ll;
        }
        __syncthreads();

        float acc[2][4][4];
        #pragma unroll
        for (int i = 0; i < 2; i++)
            #pragma unroll
            for (int j = 0; j < 4; j++)
                #pragma unroll
                for (int q = 0; q < 4; q++) acc[i][j][q] = 0.f;

        #pragma unroll
        for (int ks = 0; ks < 4; ks++) {
            const uint32_t ko = ks * 32;
            uint32_t ah[2][4], al[2][4], bb[4][2];
            #pragma unroll
            for (int mi = 0; mi < 2; mi++)
                ldm4(ah[mi][0], ah[mi][1], ah[mi][2], ah[mi][3],
                     aLM + mi * (16 * SPAD2 * 2) + ko);
            ldm4(bb[0][0], bb[1][0], bb[0][1], bb[1][1], bLM + ko);
            ldm4(bb[2][0], bb[3][0], bb[2][1], bb[3][1], bLM + 16 * SPAD2 * 2 + ko);
            #pragma unroll
            for (int mi = 0; mi < 2; mi++)
                #pragma unroll
                for (int ni = 0; ni < 4; ni++)
                    mma_bf16(acc[mi][ni], ah[mi], bb[ni]);
            #pragma unroll
            for (int mi = 0; mi < 2; mi++)
                ldm4(al[mi][0], al[mi][1], al[mi][2], al[mi][3],
                     aLM + mi * (16 * SPAD2 * 2) + ko + 128);
            #pragma unroll
            for (int mi = 0; mi < 2; mi++)
                #pragma unroll
                for (int ni = 0; ni < 4; ni++)
                    mma_bf16(acc[mi][ni], al[mi], bb[ni]);
            ldm4(bb[0][0], bb[1][0], bb[0][1], bb[1][1], bLM + ko + 128);
            ldm4(bb[2][0], bb[3][0], bb[2][1], bb[3][1], bLM + 16 * SPAD2 * 2 + ko + 128);
            #pragma unroll
            for (int mi = 0; mi < 2; mi++)
                #pragma unroll
                for (int ni = 0; ni < 4; ni++)
                    mma_bf16(acc[mi][ni], ah[mi], bb[ni]);
        }

        float* Out = Sc + ((size_t)z * TT + q0) * TT + k0;
        #pragma unroll
        for (int mi = 0; mi < 2; mi++) {
            const size_t r = wm * 32 + mi * 16 + grp;
            #pragma unroll
            for (int ni = 0; ni < 4; ni++) {
                const size_t c = wn * 32 + ni * 8 + tg * 2;
                *(float2*)(Out + r * TT + c) =
                    make_float2(acc[mi][ni][0] * 0.125f, acc[mi][ni][1] * 0.125f);
                *(float2*)(Out + (r + 8) * TT + c) =
                    make_float2(acc[mi][ni][2] * 0.125f, acc[mi][ni][3] * 0.125f);
            }
        }
        #pragma unroll
        for (int mi = 0; mi < 2; mi++) {
            #pragma unroll
            for (int half = 0; half < 2; half++) {
                const int q = q0 + wm * 32 + mi * 16 + half * 8 + grp;
                float vv[8];
                float tm = -3.0e38f;
                #pragma unroll
                for (int ni = 0; ni < 4; ni++) {
                    #pragma unroll
                    for (int e = 0; e < 2; e++) {
                        int k = k0 + wn * 32 + ni * 8 + tg * 2 + e;
                        float v = acc[mi][ni][half * 2 + e] * 0.125f;
                        int valid = causal ? (k <= q) : msk[k];
                        v = valid ? v : -1e9f;
                        vv[ni * 2 + e] = v;
                        tm = fmaxf(tm, v);
                    }
                }
                float m = ms_[mi][half];
                float nm = fmaxf(m, tm);
                float as = 0.f;
                #pragma unroll
                for (int i = 0; i < 8; i++) as += __expf(vv[i] - nm);
                ss_[mi][half] = ss_[mi][half] * __expf(m - nm) + as;
                ms_[mi][half] = nm;
            }
        }
    }

    #pragma unroll
    for (int mi = 0; mi < 2; mi++) {
        #pragma unroll
        for (int half = 0; half < 2; half++) {
            float m = ms_[mi][half], s = ss_[mi][half];
            #pragma unroll
            for (int o = 1; o <= 2; o <<= 1) {
                float mo = __shfl_xor_sync(0xffffffffu, m, o);
                float so = __shfl_xor_sync(0xffffffffu, s, o);
                float nm = fmaxf(m, mo);
                s = s * __expf(m - nm) + so * __expf(mo - nm);
                m = nm;
            }
            if (tg == 0) {
                int row = wm * 32 + mi * 16 + half * 8 + grp;
                stg[(row * 2 + wn) * 2]     = m;
                stg[(row * 2 + wn) * 2 + 1] = s;
            }
        }
    }
    __syncthreads();
    if (tid < 128) {
        float m0 = stg[(tid * 2) * 2],     s0 = stg[(tid * 2) * 2 + 1];
        float m1 = stg[(tid * 2 + 1) * 2], s1 = stg[(tid * 2 + 1) * 2 + 1];
        float M = fmaxf(m0, m1);
        float S = s0 * __expf(m0 - M) + s1 * __expf(m1 - M);
        st[((size_t)z * TT + q0 + tid) * 2]     = M;
        st[((size_t)z * TT + q0 + tid) * 2 + 1] = 1.0f / S;
    }
}

// ===================== attn @ V with fused softmax-apply =====================
#define AV_SMEM ((64 + 64) * SPAD2 * 2 + 512)
__global__ __launch_bounds__(256) void attn_av_mma(
    float* __restrict__ Sc, const __nv_bfloat16* __restrict__ VT2,
    const float* __restrict__ st, const int* __restrict__ mask,
    __nv_bfloat16* __restrict__ A2out, int causal)
{
    extern __shared__ __nv_bfloat16 sm[];
    __nv_bfloat16* As = sm;                // [64][SPAD2]  P: [hi|lo]
    __nv_bfloat16* Bs = sm + 64 * SPAD2;   // [64][SPAD2]  V^T: [hi|lo]
    float* stats = (float*)(sm + (64 + 64) * SPAD2);
    const int z = blockIdx.y, b = z >> 4, h = z & 15;
    const int q0 = blockIdx.x * 64;

    const int tid = threadIdx.x, lane = tid & 31, wid = tid >> 5;
    const int wm = wid >> 1, wn = wid & 1;
    const int grp = lane >> 2, tg = lane & 3;

    const int kend = causal ? (q0 + 64) : TT;

    if (tid < 64) {
        stats[tid]      = st[((size_t)z * TT + q0 + tid) * 2];
        stats[64 + tid] = st[((size_t)z * TT + q0 + tid) * 2 + 1];
    }
    __syncthreads();

    const __nv_bfloat16* Vt = VT2 + (size_t)z * 64 * 2048;
    const uint32_t AsU = smem_u32(As), BsU = smem_u32(Bs);
    const uint32_t aLM = AsU + (uint32_t)(((wm * 16) + (lane & 15)) * SPAD2 + (lane >> 4) * 8) * 2;
    const uint32_t bLM = BsU + (uint32_t)(((wn * 32) + (lane & 15)) * SPAD2 + (lane >> 4) * 8) * 2;

    float acc[4][4];
    #pragma unroll
    for (int i = 0; i < 4; i++)
        #pragma unroll
        for (int j = 0; j < 4; j++) acc[i][j] = 0.f;

    for (int k0 = 0; k0 < kend; k0 += 64) {
        float* Pb = Sc + ((size_t)z * TT + q0) * TT + k0;
        #pragma unroll
        for (int i = 0; i < 4; i++) {
            int f = tid + i * 256;
            int r = f >> 4, c = (f & 15) << 2;
            float4 pv = *(float4*)(Pb + (size_t)r * TT + c);
            const int qabs = q0 + r;
            const int kg = k0 + c;
            float v0, v1, v2, v3;
            if (causal) {
                v0 = (kg     <= qabs) ? pv.x : -1e9f;
                v1 = (kg + 1 <= qabs) ? pv.y : -1e9f;
                v2 = (kg + 2 <= qabs) ? pv.z : -1e9f;
                v3 = (kg + 3 <= qabs) ? pv.w : -1e9f;
            } else {
                int4 mk = *(const int4*)(mask + b * SS + kg);
                v0 = mk.x ? pv.x : -1e9f;
                v1 = mk.y ? pv.y : -1e9f;
                v2 = mk.z ? pv.z : -1e9f;
                v3 = mk.w ? pv.w : -1e9f;
            }
            const float mm = stats[r], iv = stats[64 + r];
            float p0 = __expf(v0 - mm) * iv;
            float p1 = __expf(v1 - mm) * iv;
            float p2 = __expf(v2 - mm) * iv;
            float p3 = __expf(v3 - mm) * iv;
            *(float4*)(Pb + (size_t)r * TT + c) = make_float4(p0, p1, p2, p3);
            uint2 hh, ll;
            hh.x = pack_hi2(p0, p1); hh.y = pack_hi2(p2, p3);
            ll.x = pack_lo2(p0, p1); ll.y = pack_lo2(p2, p3);
            __nv_bfloat16* R = As + r * SPAD2;
            *(uint2*)(R + c)      = hh;
            *(uint2*)(R + 64 + c) = ll;
        }
        #pragma unroll
        for (int i = 0; i < 4; i++) {
            int idx = tid + i * 256;
            int d = idx >> 4, rem = idx & 15;
            int band = rem >> 3, j = rem & 7;
            uint4 v = *(const uint4*)(Vt + (size_t)d * 2048 + band * 1024 + k0 + j * 8);
            *(uint4*)(Bs + d * SPAD2 + band * 64 + j * 8) = v;
        }
        __syncthreads();
        #pragma unroll
        for (int ks = 0; ks < 4; ks++) {
            const uint32_t ko = ks * 32;
            uint32_t ah[4], al[4], bb[4][2];
            ldm4(ah[0], ah[1], ah[2], ah[3], aLM + ko);
            ldm4(bb[0][0], bb[1][0], bb[0][1], bb[1][1], bLM + ko);
            ldm4(bb[2][0], bb[3][0], bb[2][1], bb[3][1], bLM + 16 * SPAD2 * 2 + ko);
            #pragma unroll
            for (int ni = 0; ni < 4; ni++)
                mma_bf16(acc[ni], ah, bb[ni]);
            ldm4(al[0], al[1], al[2], al[3], aLM + ko + 128);
            #pragma unroll
            for (int ni = 0; ni < 4; ni++)
                mma_bf16(acc[ni], al, bb[ni]);
            ldm4(bb[0][0], bb[1][0], bb[0][1], bb[1][1], bLM + ko + 128);
            ldm4(bb[2][0], bb[3][0], bb[2][1], bb[3][1], bLM + 16 * SPAD2 * 2 + ko + 128);
            #pragma unroll
            for (int ni = 0; ni < 4; ni++)
                mma_bf16(acc[ni], ah, bb[ni]);
        }
        __syncthreads();
    }

    if (causal && kend < TT) {
        const int Z = TT - kend;
        const int zw = Z >> 2;
        const int n4 = 64 * zw;
        const float4 z4 = make_float4(0.f, 0.f, 0.f, 0.f);
        for (int i = tid; i < n4; i += 256) {
            int r = i / zw, c = kend + (i - r * zw) * 4;
            *(float4*)(Sc + ((size_t)z * TT + q0 + r) * TT + c) = z4;
        }
    }

    const size_t m0 = (size_t)b * TT + q0 + wm * 16 + grp;
    const size_t m1 = m0 + 8;
    __nv_bfloat16* R0 = A2out + m0 * 2048;
    __nv_bfloat16* R1 = A2out + m1 * 2048;
    #pragma unroll
    for (int ni = 0; ni < 4; ni++) {
        const int cc = h * DKD + wn * 32 + ni * 8 + tg * 2;
        float v0 = acc[ni][0], v1 = acc[ni][1];
        float v2 = acc[ni][2], v3 = acc[ni][3];
        *(uint32_t*)(R0 + cc)        = pack_hi2(v0, v1);
        *(uint32_t*)(R0 + 1024 + cc) = pack_lo2(v0, v1);
        *(uint32_t*)(R1 + cc)        = pack_hi2(v2, v3);
        *(uint32_t*)(R1 + 1024 + cc) = pack_lo2(v2, v3);
    }
}

// ===================== residual add + LayerNorm =====================
__global__ __launch_bounds__(256) void add_ln(
    const float* __restrict__ X, const float* __restrict__ Dl,
    const float* __restrict__ g, const float* __restrict__ be,
    float* __restrict__ O, __nv_bfloat16* __restrict__ S2)
{
    const int row = blockIdx.x;
    const float* x  = X  + (size_t)row * DD;
    const float* dl = Dl + (size_t)row * DD;
    const int tid = threadIdx.x;

    float v[4];
    float s = 0.f;
    #pragma unroll
    for (int i = 0; i < 4; i++) {
        int c = tid + i * 256;
        v[i] = x[c] + dl[c];
        s += v[i];
    }
    __shared__ float red[8];
    #pragma unroll
    for (int o = 16; o > 0; o >>= 1) s += __shfl_xor_sync(0xffffffffu, s, o);
    if ((tid & 31) == 0) red[tid >> 5] = s;
    __syncthreads();
    s = 0.f;
    #pragma unroll
    for (int w = 0; w < 8; w++) s += red[w];
    float mean = s * (1.0f / 1024.0f);

    float qq = 0.f;
    #pragma unroll
    for (int i = 0; i < 4; i++) { float d = v[i] - mean; qq += d * d; }
    __syncthreads();
    #pragma unroll
    for (int o = 16; o > 0; o >>= 1) qq += __shfl_xor_sync(0xffffffffu, qq, o);
    if ((tid & 31) == 0) red[tid >> 5] = qq;
    __syncthreads();
    qq = 0.f;
    #pragma unroll
    for (int w = 0; w < 8; w++) qq += red[w];

    float stdv = sqrtf(qq * (1.0f / 1023.0f));
    float inv = 1.0f / (stdv + LN_EPS);
    __nv_bfloat16* R = S2 ? (S2 + (size_t)row * 2048) : (__nv_bfloat16*)0;
    #pragma unroll
    for (int i = 0; i < 4; i++) {
        int c = tid + i * 256;
        float o = g[c] * (v[i] - mean) * inv + be[c];
        O[(size_t)row * DD + c] = o;
        if (R) {
            __nv_bfloat16 h = __float2bfloat16(o);
            __nv_bfloat16 l = __float2bfloat16(o - __bfloat162float(h));
            R[c]        = h;
            R[1024 + c] = l;
        }
    }
}

// ===================== orchestration =====================
extern "C" void kernel_launch(void* const* d_in, const int* in_sizes, int n_in,
                              void* d_out, int out_size)
{
    const float* x        = (const float*)d_in[0];
    const float* enc      = (const float*)d_in[1];
    const int*   src_mask = (const int*)  d_in[2];
    const float* wq_s = (const float*)d_in[4],  *bq_s = (const float*)d_in[5];
    const float* wk_s = (const float*)d_in[6],  *bk_s = (const float*)d_in[7];
    const float* wv_s = (const float*)d_in[8],  *bv_s = (const float*)d_in[9];
    const float* wo_s = (const float*)d_in[10], *bo_s = (const float*)d_in[11];
    const float* wq_c = (const float*)d_in[12], *bq_c = (const float*)d_in[13];
    const float* wk_c = (const float*)d_in[14], *bk_c = (const float*)d_in[15];
    const float* wv_c = (const float*)d_in[16], *bv_c = (const float*)d_in[17];
    const float* w1   = (const float*)d_in[20], *b1   = (const float*)d_in[21];
    const float* w2   = (const float*)d_in[22], *b2   = (const float*)d_in[23];
    const float* g1   = (const float*)d_in[24], *be1  = (const float*)d_in[25];
    const float* g2   = (const float*)d_in[26], *be2  = (const float*)d_in[27];
    const float* g3   = (const float*)d_in[28], *be3  = (const float*)d_in[29];
    const float* bo_c2 = (const float*)d_in[19];

    float* out     = (float*)d_out;
    float* self_w  = out + (size_t)BB * TT * DD;
    float* cross_w = self_w + (size_t)BB * HH * TT * TT;

    float *QKV, *T1, *X1, *X2, *ST, *BS, *BC;
    __nv_bfloat16 *A2, *FF2, *WT2, *VT2;
    cudaGetSymbolAddress((void**)&QKV, g_qkv);
    cudaGetSymbolAddress((void**)&T1,  g_t1);
    cudaGetSymbolAddress((void**)&X1,  g_x1);
    cudaGetSymbolAddress((void**)&X2,  g_x2);
    cudaGetSymbolAddress((void**)&ST,  g_st);
    cudaGetSymbolAddress((void**)&BS,  g_bs);
    cudaGetSymbolAddress((void**)&BC,  g_bc);
    cudaGetSymbolAddress((void**)&A2,  g_a2);
    cudaGetSymbolAddress((void**)&FF2, g_ff2);
    cudaGetSymbolAddress((void**)&WT2, g_wt2);
    cudaGetSymbolAddress((void**)&VT2, g_vt2);

    cudaFuncSetAttribute(gemm_mma,        cudaFuncAttributeMaxDynamicSharedMemorySize, GEMM_SMEM);
    cudaFuncSetAttribute(attn_scores_mma, cudaFuncAttributeMaxDynamicSharedMemorySize, SCORES_SMEM);
    cudaFuncSetAttribute(attn_av_mma,     cudaFuncAttributeMaxDynamicSharedMemorySize, AV_SMEM);

    const int M = BB * TT;
    dim3 blk(256);
    dim3 gD(DD / 128, M / 128);
    dim3 gQKV(3072 / 128, M / 128);
    dim3 gKV(2048 / 128, M / 128);
    dim3 gF(DFFN / 128, M / 128);
    dim3 scoreG(TT / 128, BB * HH);
    dim3 avG(TT / 64, BB * HH);
    dim3 swG(DD / 128, DD / 32);        // split_w for [1024,1024]
    dim3 swG1(DFFN / 128, DD / 32);     // w1 [1024,4096]
    dim3 swG2(DD / 128, DFFN / 32);     // w2 [4096,1024]
    dim3 vtG(TT / 32, DD / 128, BB);
    dim3 lnG(M);
    const int ACT_BLKS = M * DD / 4 / 256;
    float* NC = (float*)0;
    __nv_bfloat16* NO3 = (__nv_bfloat16*)0;
    float* QKV2 = QKV + (size_t)M * 1024;   // cross KV region

    // ---- concat biases (graph-legal D2D copies) ----
    cudaMemcpyAsync(BS,        bq_s, 1024 * 4, cudaMemcpyDeviceToDevice);
    cudaMemcpyAsync(BS + 1024, bk_s, 1024 * 4, cudaMemcpyDeviceToDevice);
    cudaMemcpyAsync(BS + 2048, bv_s, 1024 * 4, cudaMemcpyDeviceToDevice);
    cudaMemcpyAsync(BC,        bk_c, 1024 * 4, cudaMemcpyDeviceToDevice);
    cudaMemcpyAsync(BC + 1024, bv_c, 1024 * 4, cudaMemcpyDeviceToDevice);

    // ---- self attention ----
    split_act<<<ACT_BLKS, blk>>>(x, A2);
    split_w<<<swG, blk>>>(wq_s, WT2 + 0 * W2D, DD, DD);
    split_w<<<swG, blk>>>(wk_s, WT2 + 1 * W2D, DD, DD);
    split_w<<<swG, blk>>>(wv_s, WT2 + 2 * W2D, DD, DD);
    split_w<<<swG, blk>>>(wo_s, WT2 + 3 * W2D, DD, DD);
    gemm_mma<<<gQKV, blk, GEMM_SMEM>>>(A2, WT2 + 0 * W2D, BS, QKV, NO3, 3072, 1024, 0);
    vt_split<<<vtG, blk>>>(QKV + 2048, 3072, VT2);
    attn_scores_mma<<<scoreG, blk, SCORES_SMEM>>>(QKV, 3072, QKV + 1024, 3072,
                                                  self_w, ST, src_mask, 1);
    attn_av_mma<<<avG, blk, AV_SMEM>>>(self_w, VT2, ST, src_mask, A2, 1);
    gemm_mma<<<gD, blk, GEMM_SMEM>>>(A2, WT2 + 3 * W2D, bo_s, T1, NO3, DD, 1024, 0);
    add_ln<<<lnG, blk>>>(x, T1, g1, be1, X1, A2);

    // ---- remaining weight splits ----
    split_w<<<swG, blk>>>(wq_c, WT2 + 4 * W2D, DD, DD);
    split_w<<<swG, blk>>>(wk_c, WT2 + 5 * W2D, DD, DD);
    split_w<<<swG, blk>>>(wv_c, WT2 + 6 * W2D, DD, DD);
    split_w<<<swG, blk>>>((const float*)d_in[18], WT2 + 7 * W2D, DD, DD);
    split_w<<<swG1, blk>>>(w1, WT2 + W1OFF, DD, DFFN);
    split_w<<<swG2, blk>>>(w2, WT2 + W2OFF, DFFN, DD);

    // ---- cross attention ----
    gemm_mma<<<gD, blk, GEMM_SMEM>>>(A2, WT2 + 4 * W2D, bq_c, QKV, NO3, DD, 1024, 0);
    split_act<<<ACT_BLKS, blk>>>(enc, A2);
    gemm_mma<<<gKV, blk, GEMM_SMEM>>>(A2, WT2 + 5 * W2D, BC, QKV2, NO3, 2048, 1024, 0);
    vt_split<<<vtG, blk>>>(QKV2 + 1024, 2048, VT2);
    attn_scores_mma<<<scoreG, blk, SCORES_SMEM>>>(QKV, 1024, QKV2, 2048,
                                                  cross_w, ST, src_mask, 0);
    attn_av_mma<<<avG, blk, AV_SMEM>>>(cross_w, VT2, ST, src_mask, A2, 0);
    gemm_mma<<<gD, blk, GEMM_SMEM>>>(A2, WT2 + 7 * W2D, bo_c2, T1, NO3, DD, 1024, 0);
    add_ln<<<lnG, blk>>>(X1, T1, g2, be2, X2, A2);

    // ---- feed-forward ----
    gemm_mma<<<gF, blk, GEMM_SMEM>>>(A2, WT2 + W1OFF, b1, NC, FF2, DFFN, 1024, 1);
    gemm_mma<<<gD, blk, GEMM_SMEM>>>(FF2, WT2 + W2OFF, b2, T1, NO3, DD, 4096, 0);
    add_ln<<<lnG, blk>>>(X2, T1, g3, be3, out, NO3);

    (void)in_sizes; (void)n_in; (void)out_size; (void)bv_c;
}

// round 17
// speedup vs baseline: 1.1006x; 1.0363x over previous
#include <cuda_runtime.h>
#include <cuda_bf16.h>
#include <math.h>
#include <stdint.h>

#define BB 4
#define TT 1024
#define SS 1024
#define DD 1024
#define HH 16
#define DKD 64
#define DFFN 4096
#define LN_EPS 1e-6f

// ===================== scratch (no allocations) =====================
__device__ float g_qkv[4096ULL * 3072];           // self QKV / cross Q
__device__ float g_kvc[4096ULL * 2048];           // cross KV (stream 2)
__device__ float g_t1[BB*TT*DD];
__device__ float g_x1[BB*TT*DD];
__device__ float g_x2[BB*TT*DD];
__device__ float g_st[64ULL * 1024 * 2];          // per (z,q): max, inv_sum
__device__ float g_bs[3072];                      // concat bias self QKV
__device__ float g_bc[2048];                      // concat bias cross KV

__device__ __nv_bfloat16 g_a2 [4096ULL * 2048];   // activations [M,2K] (hi|lo)
__device__ __nv_bfloat16 g_e2 [4096ULL * 2048];   // enc split (stream 2)
__device__ __nv_bfloat16 g_ff2[4096ULL * 8192];   // FF activations (hi|lo)
__device__ __nv_bfloat16 g_vt2 [4096ULL * 2048];  // self V^T split
__device__ __nv_bfloat16 g_vt2c[4096ULL * 2048];  // cross V^T split (stream 2)
#define W2D (1024ULL*2048)
#define W1OFF (8*W2D)
#define W2OFF (8*W2D + 4096ULL*2048)
__device__ __nv_bfloat16 g_wt2[8*W2D + 4096ULL*2048 + 1024ULL*8192];

// ===================== helpers =====================
__device__ __forceinline__ uint32_t pack_hi2(float x, float y) {
    __nv_bfloat16 a = __float2bfloat16(x), b = __float2bfloat16(y);
    return (uint32_t)__bfloat16_as_ushort(a) | ((uint32_t)__bfloat16_as_ushort(b) << 16);
}
__device__ __forceinline__ uint32_t pack_lo2(float x, float y) {
    __nv_bfloat16 a = __float2bfloat16(x), b = __float2bfloat16(y);
    __nv_bfloat16 ra = __float2bfloat16(x - __bfloat162float(a));
    __nv_bfloat16 rb = __float2bfloat16(y - __bfloat162float(b));
    return (uint32_t)__bfloat16_as_ushort(ra) | ((uint32_t)__bfloat16_as_ushort(rb) << 16);
}
__device__ __forceinline__ void mma_bf16(
    float* d, const uint32_t* a, const uint32_t* b)
{
    asm volatile(
        "mma.sync.aligned.m16n8k16.row.col.f32.bf16.bf16.f32 "
        "{%0,%1,%2,%3}, {%4,%5,%6,%7}, {%8,%9}, {%0,%1,%2,%3};"
        : "+f"(d[0]), "+f"(d[1]), "+f"(d[2]), "+f"(d[3])
        : "r"(a[0]), "r"(a[1]), "r"(a[2]), "r"(a[3]), "r"(b[0]), "r"(b[1]));
}
__device__ __forceinline__ uint32_t smem_u32(const void* p) {
    uint32_t a;
    asm("{ .reg .u64 t; cvta.to.shared.u64 t, %1; cvt.u32.u64 %0, t; }" : "=r"(a) : "l"(p));
    return a;
}
__device__ __forceinline__ void cp16(uint32_t s, const void* g) {
    asm volatile("cp.async.cg.shared.global [%0], [%1], 16;" :: "r"(s), "l"(g));
}
#define CP_COMMIT() asm volatile("cp.async.commit_group;" ::: "memory")
#define CP_WAIT1()  asm volatile("cp.async.wait_group 1;" ::: "memory")
__device__ __forceinline__ void ldm4(uint32_t& r0, uint32_t& r1, uint32_t& r2, uint32_t& r3, uint32_t a) {
    asm volatile("ldmatrix.sync.aligned.m8n8.x4.shared.b16 {%0,%1,%2,%3}, [%4];"
        : "=r"(r0), "=r"(r1), "=r"(r2), "=r"(r3) : "r"(a));
}

// ===================== split/convert kernels =====================
__global__ __launch_bounds__(256) void split_act(
    const float* __restrict__ A, __nv_bfloat16* __restrict__ O)
{
    const int K = 1024;
    size_t idx = (size_t)blockIdx.x * 256 + threadIdx.x;
    size_t base = idx << 2;
    size_t m = base >> 10;
    int k = (int)(base & (size_t)(K - 1));
    float4 v = *(const float4*)(A + base);
    uint2 hh, ll;
    hh.x = pack_hi2(v.x, v.y); hh.y = pack_hi2(v.z, v.w);
    ll.x = pack_lo2(v.x, v.y); ll.y = pack_lo2(v.z, v.w);
    __nv_bfloat16* row = O + m * (size_t)(2 * K);
    *(uint2*)(row + k)     = hh;
    *(uint2*)(row + K + k) = ll;
}

__global__ __launch_bounds__(256) void split_w(
    const float* __restrict__ W, __nv_bfloat16* __restrict__ O, int K, int N)
{
    __shared__ float t[32][133];
    const int k0 = blockIdx.y * 32;
    const int n0 = blockIdx.x * 128;
    const int tid = threadIdx.x;

    #pragma unroll
    for (int i = 0; i < 4; i++) {
        int idx = tid + i * 256;
        int row = idx >> 5, c4 = (idx & 31) << 2;
        float4 v = *(const float4*)(W + (size_t)(k0 + row) * N + n0 + c4);
        t[row][c4] = v.x; t[row][c4 + 1] = v.y;
        t[row][c4 + 2] = v.z; t[row][c4 + 3] = v.w;
    }
    __syncthreads();

    #pragma unroll
    for (int i = 0; i < 4; i++) {
        int idx = tid + i * 256;
        int nn = idx >> 3, kg = (idx & 7) << 2;
        float v0 = t[kg][nn], v1 = t[kg + 1][nn];
        float v2 = t[kg + 2][nn], v3 = t[kg + 3][nn];
        uint2 hh, ll;
        hh.x = pack_hi2(v0, v1); hh.y = pack_hi2(v2, v3);
        ll.x = pack_lo2(v0, v1); ll.y = pack_lo2(v2, v3);
        size_t ro = (size_t)(n0 + nn) * (size_t)(2 * K) + k0 + kg;
        *(uint2*)(O + ro)     = hh;
        *(uint2*)(O + ro + K) = ll;
    }
}

__global__ __launch_bounds__(256) void vt_split(
    const float* __restrict__ V, int vstr, __nv_bfloat16* __restrict__ VT2)
{
    __shared__ float t[32][133];
    const int b = blockIdx.z;
    const int k0 = blockIdx.x * 32;
    const int d0 = blockIdx.y * 128;
    const int tid = threadIdx.x;

    #pragma unroll
    for (int i = 0; i < 4; i++) {
        int idx = tid + i * 256;
        int row = idx >> 5, c4 = (idx & 31) << 2;
        float4 v = *(const float4*)(V + (size_t)(b * TT + k0 + row) * vstr + d0 + c4);
        t[row][c4] = v.x; t[row][c4 + 1] = v.y;
        t[row][c4 + 2] = v.z; t[row][c4 + 3] = v.w;
    }
    __syncthreads();

    #pragma unroll
    for (int i = 0; i < 4; i++) {
        int idx = tid + i * 256;
        int dd = idx >> 3, kg = (idx & 7) << 2;
        int dg = d0 + dd;
        int hh_ = dg >> 6, dk = dg & 63;
        size_t row = ((size_t)(b * HH + hh_) * 64 + dk) * 2048;
        float v0 = t[kg][dd], v1 = t[kg + 1][dd];
        float v2 = t[kg + 2][dd], v3 = t[kg + 3][dd];
        uint2 hh, ll;
        hh.x = pack_hi2(v0, v1); hh.y = pack_hi2(v2, v3);
        ll.x = pack_lo2(v0, v1); ll.y = pack_lo2(v2, v3);
        *(uint2*)(VT2 + row + k0 + kg)        = hh;
        *(uint2*)(VT2 + row + 1024 + k0 + kg) = ll;
    }
}

// ===================== HMMA GEMM, 2-segment operands, 3 products in-smem ====
#define PADK2 72
#define TSTG (128 * PADK2 * 2)
#define SSTG (2 * TSTG)
#define STAGES2 3
#define GEMM_SMEM (STAGES2 * SSTG)

__global__ __launch_bounds__(256) void gemm_mma(
    const __nv_bfloat16* __restrict__ A2, const __nv_bfloat16* __restrict__ W2,
    const float* __restrict__ bias, float* __restrict__ C,
    __nv_bfloat16* __restrict__ O3, int N, int Kl, int relu)
{
    extern __shared__ char dsm[];
    const uint32_t sb = smem_u32(dsm);
    const int tid = threadIdx.x;
    const int lane = tid & 31, wid = tid >> 5;
    const int wm = wid >> 2, wn = wid & 3;
    const int grp = lane >> 2, tg = lane & 3;

    const size_t arow0 = (size_t)blockIdx.y * 128;
    const size_t bcol0 = (size_t)blockIdx.x * 128;
    const size_t rstr = (size_t)2 * Kl;

    const uint32_t aLM = (uint32_t)(((wm * 64) + (lane & 15)) * PADK2 + (lane >> 4) * 8) * 2;
    const uint32_t bLM = (uint32_t)(((wn * 32) + (lane & 15)) * PADK2 + (lane >> 4) * 8) * 2;

    float acc[4][4][4];
    #pragma unroll
    for (int i = 0; i < 4; i++)
        #pragma unroll
        for (int j = 0; j < 4; j++)
            #pragma unroll
            for (int q = 0; q < 4; q++) acc[i][j][q] = 0.f;

    const int NC = Kl >> 5;

    auto issue = [&](int c, int st) {
        const uint32_t ab = sb + st * SSTG;
        const uint32_t bb = ab + TSTG;
        #pragma unroll
        for (int i = 0; i < 4; i++) {
            int idx = tid + i * 256;
            int r = idx >> 3, s = idx & 7;
            size_t go = (s < 4) ? ((size_t)c * 32 + s * 8)
                                : ((size_t)Kl + c * 32 + (s - 4) * 8);
            uint32_t so = (uint32_t)(r * PADK2 + s * 8) * 2;
            cp16(ab + so, A2 + (arow0 + r) * rstr + go);
            cp16(bb + so, W2 + (bcol0 + r) * rstr + go);
        }
        CP_COMMIT();
    };

    issue(0, 0); issue(1, 1);

    int st = 0;
    for (int c = 0; c < NC; c++) {
        CP_WAIT1();
        __syncthreads();
        if (c + 2 < NC) {
            int ns = st + 2; if (ns >= 3) ns -= 3;
            issue(c + 2, ns);
        } else CP_COMMIT();

        const uint32_t As0 = sb + st * SSTG;
        const uint32_t Bs0 = As0 + TSTG;
        #pragma unroll
        for (int ks = 0; ks < 2; ks++) {
            const uint32_t ko = ks * 32;
            uint32_t ah[4][4], al[4][4], b2[4][2];
            #pragma unroll
            for (int ms = 0; ms < 4; ms++)
                ldm4(ah[ms][0], ah[ms][1], ah[ms][2], ah[ms][3],
                     As0 + aLM + ms * (16 * PADK2 * 2) + ko);
            ldm4(b2[0][0], b2[1][0], b2[0][1], b2[1][1], Bs0 + bLM + ko);
            ldm4(b2[2][0], b2[3][0], b2[2][1], b2[3][1], Bs0 + bLM + 16 * PADK2 * 2 + ko);
            #pragma unroll
            for (int ms = 0; ms < 4; ms++)
                #pragma unroll
                for (int ns = 0; ns < 4; ns++)
                    mma_bf16(acc[ms][ns], ah[ms], b2[ns]);
            #pragma unroll
            for (int ms = 0; ms < 4; ms++)
                ldm4(al[ms][0], al[ms][1], al[ms][2], al[ms][3],
                     As0 + aLM + ms * (16 * PADK2 * 2) + ko + 64);
            #pragma unroll
            for (int ms = 0; ms < 4; ms++)
                #pragma unroll
                for (int ns = 0; ns < 4; ns++)
                    mma_bf16(acc[ms][ns], al[ms], b2[ns]);
            ldm4(b2[0][0], b2[1][0], b2[0][1], b2[1][1], Bs0 + bLM + ko + 64);
            ldm4(b2[2][0], b2[3][0], b2[2][1], b2[3][1], Bs0 + bLM + 16 * PADK2 * 2 + ko + 64);
            #pragma unroll
            for (int ms = 0; ms < 4; ms++)
                #pragma unroll
                for (int ns = 0; ns < 4; ns++)
                    mma_bf16(acc[ms][ns], ah[ms], b2[ns]);
        }
        if (++st >= 3) st = 0;
    }

    if (O3) {
        const size_t ostr = (size_t)2 * N;
        #pragma unroll
        for (int ms = 0; ms < 4; ms++) {
            const size_t rr0 = arow0 + wm * 64 + ms * 16 + grp;
            #pragma unroll
            for (int ns = 0; ns < 4; ns++) {
                const size_t cc = bcol0 + wn * 32 + ns * 8 + tg * 2;
                float bx = bias[cc], by = bias[cc + 1];
                float v0 = fmaxf(acc[ms][ns][0] + bx, 0.f);
                float v1 = fmaxf(acc[ms][ns][1] + by, 0.f);
                float v2 = fmaxf(acc[ms][ns][2] + bx, 0.f);
                float v3 = fmaxf(acc[ms][ns][3] + by, 0.f);
                __nv_bfloat16* R0 = O3 + rr0 * ostr;
                __nv_bfloat16* R1 = O3 + (rr0 + 8) * ostr;
                *(uint32_t*)(R0 + cc)     = pack_hi2(v0, v1);
                *(uint32_t*)(R0 + N + cc) = pack_lo2(v0, v1);
                *(uint32_t*)(R1 + cc)     = pack_hi2(v2, v3);
                *(uint32_t*)(R1 + N + cc) = pack_lo2(v2, v3);
            }
        }
    } else {
        #pragma unroll
        for (int ms = 0; ms < 4; ms++) {
            const size_t rr0 = arow0 + wm * 64 + ms * 16 + grp;
            #pragma unroll
            for (int ns = 0; ns < 4; ns++) {
                const size_t cc = bcol0 + wn * 32 + ns * 8 + tg * 2;
                float bx = bias[cc], by = bias[cc + 1];
                float v0 = acc[ms][ns][0] + bx;
                float v1 = acc[ms][ns][1] + by;
                float v2 = acc[ms][ns][2] + bx;
                float v3 = acc[ms][ns][3] + by;
                if (relu) {
                    v0 = fmaxf(v0, 0.f); v1 = fmaxf(v1, 0.f);
                    v2 = fmaxf(v2, 0.f); v3 = fmaxf(v3, 0.f);
                }
                *(float2*)(C + rr0 * N + cc)       = make_float2(v0, v1);
                *(float2*)(C + (rr0 + 8) * N + cc) = make_float2(v2, v3);
            }
        }
    }
}

// ===================== attention scores + fused softmax stats ======
#define SPAD2 136
#define SCORES_SMEM ((128 + 64) * SPAD2 * 2 + 128 * 16 + 4096)
__global__ __launch_bounds__(256) void attn_scores_mma(
    const float* __restrict__ Q, int qstr,
    const float* __restrict__ Kv, int kstr,
    float* __restrict__ Sc, float* __restrict__ st,
    const int* __restrict__ mask, int causal)
{
    extern __shared__ __nv_bfloat16 sm[];
    __nv_bfloat16* As = sm;                 // [128][SPAD2]  Q: [hi|lo]
    __nv_bfloat16* Bs = sm + 128 * SPAD2;   // [64][SPAD2]   K: [hi|lo]
    float* stg = (float*)(sm + (128 + 64) * SPAD2);   // [128][2][2]
    int*   msk = (int*)(stg + 128 * 4);               // [1024]
    const int z = blockIdx.y, b = z >> 4, h = z & 15;
    const int q0 = blockIdx.x * 128;

    const int tid = threadIdx.x, lane = tid & 31, wid = tid >> 5;
    const int wm = wid >> 1, wn = wid & 1;
    const int grp = lane >> 2, tg = lane & 3;

    const float* Qb = Q + ((size_t)(b * TT + q0)) * qstr + h * DKD;

    #pragma unroll
    for (int i = 0; i < 8; i++) {
        int f = tid + i * 256;
        int r = f >> 4, c = (f & 15) << 2;
        float4 v = *(const float4*)(Qb + (size_t)r * qstr + c);
        uint2 hh, ll;
        hh.x = pack_hi2(v.x, v.y); hh.y = pack_hi2(v.z, v.w);
        ll.x = pack_lo2(v.x, v.y); ll.y = pack_lo2(v.z, v.w);
        __nv_bfloat16* R = As + r * SPAD2;
        *(uint2*)(R + c)      = hh;
        *(uint2*)(R + 64 + c) = ll;
    }
    if (!causal) {
        #pragma unroll
        for (int i = 0; i < 4; i++) msk[tid + i * 256] = mask[b * SS + tid + i * 256];
    }

    const uint32_t AsU = smem_u32(As), BsU = smem_u32(Bs);
    const uint32_t aLM = AsU + (uint32_t)(((wm * 32) + (lane & 15)) * SPAD2 + (lane >> 4) * 8) * 2;
    const uint32_t bLM = BsU + (uint32_t)(((wn * 32) + (lane & 15)) * SPAD2 + (lane >> 4) * 8) * 2;

    float ms_[2][2] = {{-3.0e38f, -3.0e38f}, {-3.0e38f, -3.0e38f}};
    float ss_[2][2] = {{0.f, 0.f}, {0.f, 0.f}};
    const int ktend = causal ? ((q0 >> 6) + 2) : 16;

    for (int kt = 0; kt < ktend; kt++) {
        const int k0 = kt * 64;
        __syncthreads();
        const float* Kb = Kv + ((size_t)(b * TT + k0)) * kstr + h * DKD;
        #pragma unroll
        for (int i = 0; i < 4; i++) {
            int f = tid + i * 256;
            int r = f >> 4, c = (f & 15) << 2;
            float4 v = *(const float4*)(Kb + (size_t)r * kstr + c);
            uint2 hh, ll;
            hh.x = pack_hi2(v.x, v.y); hh.y = pack_hi2(v.z, v.w);
            ll.x = pack_lo2(v.x, v.y); ll.y = pack_lo2(v.z, v.w);
            __nv_bfloat16* R = Bs + r * SPAD2;
            *(uint2*)(R + c)      = hh;
            *(uint2*)(R + 64 + c) = ll;
        }
        __syncthreads();

        float acc[2][4][4];
        #pragma unroll
        for (int i = 0; i < 2; i++)
            #pragma unroll
            for (int j = 0; j < 4; j++)
                #pragma unroll
                for (int q = 0; q < 4; q++) acc[i][j][q] = 0.f;

        #pragma unroll
        for (int ks = 0; ks < 4; ks++) {
            const uint32_t ko = ks * 32;
            uint32_t ah[2][4], al[2][4], bb[4][2];
            #pragma unroll
            for (int mi = 0; mi < 2; mi++)
                ldm4(ah[mi][0], ah[mi][1], ah[mi][2], ah[mi][3],
                     aLM + mi * (16 * SPAD2 * 2) + ko);
            ldm4(bb[0][0], bb[1][0], bb[0][1], bb[1][1], bLM + ko);
            ldm4(bb[2][0], bb[3][0], bb[2][1], bb[3][1], bLM + 16 * SPAD2 * 2 + ko);
            #pragma unroll
            for (int mi = 0; mi < 2; mi++)
                #pragma unroll
                for (int ni = 0; ni < 4; ni++)
                    mma_bf16(acc[mi][ni], ah[mi], bb[ni]);
            #pragma unroll
            for (int mi = 0; mi < 2; mi++)
                ldm4(al[mi][0], al[mi][1], al[mi][2], al[mi][3],
                     aLM + mi * (16 * SPAD2 * 2) + ko + 128);
            #pragma unroll
            for (int mi = 0; mi < 2; mi++)
                #pragma unroll
                for (int ni = 0; ni < 4; ni++)
                    mma_bf16(acc[mi][ni], al[mi], bb[ni]);
            ldm4(bb[0][0], bb[1][0], bb[0][1], bb[1][1], bLM + ko + 128);
            ldm4(bb[2][0], bb[3][0], bb[2][1], bb[3][1], bLM + 16 * SPAD2 * 2 + ko + 128);
            #pragma unroll
            for (int mi = 0; mi < 2; mi++)
                #pragma unroll
                for (int ni = 0; ni < 4; ni++)
                    mma_bf16(acc[mi][ni], ah[mi], bb[ni]);
        }

        float* Out = Sc + ((size_t)z * TT + q0) * TT + k0;
        #pragma unroll
        for (int mi = 0; mi < 2; mi++) {
            const size_t r = wm * 32 + mi * 16 + grp;
            #pragma unroll
            for (int ni = 0; ni < 4; ni++) {
                const size_t c = wn * 32 + ni * 8 + tg * 2;
                *(float2*)(Out + r * TT + c) =
                    make_float2(acc[mi][ni][0] * 0.125f, acc[mi][ni][1] * 0.125f);
                *(float2*)(Out + (r + 8) * TT + c) =
                    make_float2(acc[mi][ni][2] * 0.125f, acc[mi][ni][3] * 0.125f);
            }
        }
        #pragma unroll
        for (int mi = 0; mi < 2; mi++) {
            #pragma unroll
            for (int half = 0; half < 2; half++) {
                const int q = q0 + wm * 32 + mi * 16 + half * 8 + grp;
                float vv[8];
                float tm = -3.0e38f;
                #pragma unroll
                for (int ni = 0; ni < 4; ni++) {
                    #pragma unroll
                    for (int e = 0; e < 2; e++) {
                        int k = k0 + wn * 32 + ni * 8 + tg * 2 + e;
                        float v = acc[mi][ni][half * 2 + e] * 0.125f;
                        int valid = causal ? (k <= q) : msk[k];
                        v = valid ? v : -1e9f;
                        vv[ni * 2 + e] = v;
                        tm = fmaxf(tm, v);
                    }
                }
                float m = ms_[mi][half];
                float nm = fmaxf(m, tm);
                float as = 0.f;
                #pragma unroll
                for (int i = 0; i < 8; i++) as += __expf(vv[i] - nm);
                ss_[mi][half] = ss_[mi][half] * __expf(m - nm) + as;
                ms_[mi][half] = nm;
            }
        }
    }

    #pragma unroll
    for (int mi = 0; mi < 2; mi++) {
        #pragma unroll
        for (int half = 0; half < 2; half++) {
            float m = ms_[mi][half], s = ss_[mi][half];
            #pragma unroll
            for (int o = 1; o <= 2; o <<= 1) {
                float mo = __shfl_xor_sync(0xffffffffu, m, o);
                float so = __shfl_xor_sync(0xffffffffu, s, o);
                float nm = fmaxf(m, mo);
                s = s * __expf(m - nm) + so * __expf(mo - nm);
                m = nm;
            }
            if (tg == 0) {
                int row = wm * 32 + mi * 16 + half * 8 + grp;
                stg[(row * 2 + wn) * 2]     = m;
                stg[(row * 2 + wn) * 2 + 1] = s;
            }
        }
    }
    __syncthreads();
    if (tid < 128) {
        float m0 = stg[(tid * 2) * 2],     s0 = stg[(tid * 2) * 2 + 1];
        float m1 = stg[(tid * 2 + 1) * 2], s1 = stg[(tid * 2 + 1) * 2 + 1];
        float M = fmaxf(m0, m1);
        float S = s0 * __expf(m0 - M) + s1 * __expf(m1 - M);
        st[((size_t)z * TT + q0 + tid) * 2]     = M;
        st[((size_t)z * TT + q0 + tid) * 2 + 1] = 1.0f / S;
    }
}

// ===================== attn @ V with fused softmax-apply =====================
#define AV_SMEM ((64 + 64) * SPAD2 * 2 + 512)
__global__ __launch_bounds__(256) void attn_av_mma(
    float* __restrict__ Sc, const __nv_bfloat16* __restrict__ VT2,
    const float* __restrict__ st, const int* __restrict__ mask,
    __nv_bfloat16* __restrict__ A2out, int causal)
{
    extern __shared__ __nv_bfloat16 sm[];
    __nv_bfloat16* As = sm;                // [64][SPAD2]  P: [hi|lo]
    __nv_bfloat16* Bs = sm + 64 * SPAD2;   // [64][SPAD2]  V^T: [hi|lo]
    float* stats = (float*)(sm + (64 + 64) * SPAD2);
    const int z = blockIdx.y, b = z >> 4, h = z & 15;
    const int q0 = blockIdx.x * 64;

    const int tid = threadIdx.x, lane = tid & 31, wid = tid >> 5;
    const int wm = wid >> 1, wn = wid & 1;
    const int grp = lane >> 2, tg = lane & 3;

    const int kend = causal ? (q0 + 64) : TT;

    if (tid < 64) {
        stats[tid]      = st[((size_t)z * TT + q0 + tid) * 2];
        stats[64 + tid] = st[((size_t)z * TT + q0 + tid) * 2 + 1];
    }
    __syncthreads();

    const __nv_bfloat16* Vt = VT2 + (size_t)z * 64 * 2048;
    const uint32_t AsU = smem_u32(As), BsU = smem_u32(Bs);
    const uint32_t aLM = AsU + (uint32_t)(((wm * 16) + (lane & 15)) * SPAD2 + (lane >> 4) * 8) * 2;
    const uint32_t bLM = BsU + (uint32_t)(((wn * 32) + (lane & 15)) * SPAD2 + (lane >> 4) * 8) * 2;

    float acc[4][4];
    #pragma unroll
    for (int i = 0; i < 4; i++)
        #pragma unroll
        for (int j = 0; j < 4; j++) acc[i][j] = 0.f;

    for (int k0 = 0; k0 < kend; k0 += 64) {
        float* Pb = Sc + ((size_t)z * TT + q0) * TT + k0;
        #pragma unroll
        for (int i = 0; i < 4; i++) {
            int f = tid + i * 256;
            int r = f >> 4, c = (f & 15) << 2;
            float4 pv = *(float4*)(Pb + (size_t)r * TT + c);
            const int qabs = q0 + r;
            const int kg = k0 + c;
            float v0, v1, v2, v3;
            if (causal) {
                v0 = (kg     <= qabs) ? pv.x : -1e9f;
                v1 = (kg + 1 <= qabs) ? pv.y : -1e9f;
                v2 = (kg + 2 <= qabs) ? pv.z : -1e9f;
                v3 = (kg + 3 <= qabs) ? pv.w : -1e9f;
            } else {
                int4 mk = *(const int4*)(mask + b * SS + kg);
                v0 = mk.x ? pv.x : -1e9f;
                v1 = mk.y ? pv.y : -1e9f;
                v2 = mk.z ? pv.z : -1e9f;
                v3 = mk.w ? pv.w : -1e9f;
            }
            const float mm = stats[r], iv = stats[64 + r];
            float p0 = __expf(v0 - mm) * iv;
            float p1 = __expf(v1 - mm) * iv;
            float p2 = __expf(v2 - mm) * iv;
            float p3 = __expf(v3 - mm) * iv;
            *(float4*)(Pb + (size_t)r * TT + c) = make_float4(p0, p1, p2, p3);
            uint2 hh, ll;
            hh.x = pack_hi2(p0, p1); hh.y = pack_hi2(p2, p3);
            ll.x = pack_lo2(p0, p1); ll.y = pack_lo2(p2, p3);
            __nv_bfloat16* R = As + r * SPAD2;
            *(uint2*)(R + c)      = hh;
            *(uint2*)(R + 64 + c) = ll;
        }
        #pragma unroll
        for (int i = 0; i < 4; i++) {
            int idx = tid + i * 256;
            int d = idx >> 4, rem = idx & 15;
            int band = rem >> 3, j = rem & 7;
            uint4 v = *(const uint4*)(Vt + (size_t)d * 2048 + band * 1024 + k0 + j * 8);
            *(uint4*)(Bs + d * SPAD2 + band * 64 + j * 8) = v;
        }
        __syncthreads();
        #pragma unroll
        for (int ks = 0; ks < 4; ks++) {
            const uint32_t ko = ks * 32;
            uint32_t ah[4], al[4], bb[4][2];
            ldm4(ah[0], ah[1], ah[2], ah[3], aLM + ko);
            ldm4(bb[0][0], bb[1][0], bb[0][1], bb[1][1], bLM + ko);
            ldm4(bb[2][0], bb[3][0], bb[2][1], bb[3][1], bLM + 16 * SPAD2 * 2 + ko);
            #pragma unroll
            for (int ni = 0; ni < 4; ni++)
                mma_bf16(acc[ni], ah, bb[ni]);
            ldm4(al[0], al[1], al[2], al[3], aLM + ko + 128);
            #pragma unroll
            for (int ni = 0; ni < 4; ni++)
                mma_bf16(acc[ni], al, bb[ni]);
            ldm4(bb[0][0], bb[1][0], bb[0][1], bb[1][1], bLM + ko + 128);
            ldm4(bb[2][0], bb[3][0], bb[2][1], bb[3][1], bLM + 16 * SPAD2 * 2 + ko + 128);
            #pragma unroll
            for (int ni = 0; ni < 4; ni++)
                mma_bf16(acc[ni], ah, bb[ni]);
        }
        __syncthreads();
    }

    if (causal && kend < TT) {
        const int Z = TT - kend;
        const int zw = Z >> 2;
        const int n4 = 64 * zw;
        const float4 z4 = make_float4(0.f, 0.f, 0.f, 0.f);
        for (int i = tid; i < n4; i += 256) {
            int r = i / zw, c = kend + (i - r * zw) * 4;
            *(float4*)(Sc + ((size_t)z * TT + q0 + r) * TT + c) = z4;
        }
    }

    const size_t m0 = (size_t)b * TT + q0 + wm * 16 + grp;
    const size_t m1 = m0 + 8;
    __nv_bfloat16* R0 = A2out + m0 * 2048;
    __nv_bfloat16* R1 = A2out + m1 * 2048;
    #pragma unroll
    for (int ni = 0; ni < 4; ni++) {
        const int cc = h * DKD + wn * 32 + ni * 8 + tg * 2;
        float v0 = acc[ni][0], v1 = acc[ni][1];
        float v2 = acc[ni][2], v3 = acc[ni][3];
        *(uint32_t*)(R0 + cc)        = pack_hi2(v0, v1);
        *(uint32_t*)(R0 + 1024 + cc) = pack_lo2(v0, v1);
        *(uint32_t*)(R1 + cc)        = pack_hi2(v2, v3);
        *(uint32_t*)(R1 + 1024 + cc) = pack_lo2(v2, v3);
    }
}

// ===================== residual add + LayerNorm =====================
__global__ __launch_bounds__(256) void add_ln(
    const float* __restrict__ X, const float* __restrict__ Dl,
    const float* __restrict__ g, const float* __restrict__ be,
    float* __restrict__ O, __nv_bfloat16* __restrict__ S2)
{
    const int row = blockIdx.x;
    const float* x  = X  + (size_t)row * DD;
    const float* dl = Dl + (size_t)row * DD;
    const int tid = threadIdx.x;

    float v[4];
    float s = 0.f;
    #pragma unroll
    for (int i = 0; i < 4; i++) {
        int c = tid + i * 256;
        v[i] = x[c] + dl[c];
        s += v[i];
    }
    __shared__ float red[8];
    #pragma unroll
    for (int o = 16; o > 0; o >>= 1) s += __shfl_xor_sync(0xffffffffu, s, o);
    if ((tid & 31) == 0) red[tid >> 5] = s;
    __syncthreads();
    s = 0.f;
    #pragma unroll
    for (int w = 0; w < 8; w++) s += red[w];
    float mean = s * (1.0f / 1024.0f);

    float qq = 0.f;
    #pragma unroll
    for (int i = 0; i < 4; i++) { float d = v[i] - mean; qq += d * d; }
    __syncthreads();
    #pragma unroll
    for (int o = 16; o > 0; o >>= 1) qq += __shfl_xor_sync(0xffffffffu, qq, o);
    if ((tid & 31) == 0) red[tid >> 5] = qq;
    __syncthreads();
    qq = 0.f;
    #pragma unroll
    for (int w = 0; w < 8; w++) qq += red[w];

    float stdv = sqrtf(qq * (1.0f / 1023.0f));
    float inv = 1.0f / (stdv + LN_EPS);
    __nv_bfloat16* R = S2 ? (S2 + (size_t)row * 2048) : (__nv_bfloat16*)0;
    #pragma unroll
    for (int i = 0; i < 4; i++) {
        int c = tid + i * 256;
        float o = g[c] * (v[i] - mean) * inv + be[c];
        O[(size_t)row * DD + c] = o;
        if (R) {
            __nv_bfloat16 h = __float2bfloat16(o);
            __nv_bfloat16 l = __float2bfloat16(o - __bfloat162float(h));
            R[c]        = h;
            R[1024 + c] = l;
        }
    }
}

// ===================== orchestration =====================
extern "C" void kernel_launch(void* const* d_in, const int* in_sizes, int n_in,
                              void* d_out, int out_size)
{
    const float* x        = (const float*)d_in[0];
    const float* enc      = (const float*)d_in[1];
    const int*   src_mask = (const int*)  d_in[2];
    const float* wq_s = (const float*)d_in[4],  *bq_s = (const float*)d_in[5];
    const float* wk_s = (const float*)d_in[6],  *bk_s = (const float*)d_in[7];
    const float* wv_s = (const float*)d_in[8],  *bv_s = (const float*)d_in[9];
    const float* wo_s = (const float*)d_in[10], *bo_s = (const float*)d_in[11];
    const float* wq_c = (const float*)d_in[12], *bq_c = (const float*)d_in[13];
    const float* wk_c = (const float*)d_in[14], *bk_c = (const float*)d_in[15];
    const float* wv_c = (const float*)d_in[16], *bv_c = (const float*)d_in[17];
    const float* w1   = (const float*)d_in[20], *b1   = (const float*)d_in[21];
    const float* w2   = (const float*)d_in[22], *b2   = (const float*)d_in[23];
    const float* g1   = (const float*)d_in[24], *be1  = (const float*)d_in[25];
    const float* g2   = (const float*)d_in[26], *be2  = (const float*)d_in[27];
    const float* g3   = (const float*)d_in[28], *be3  = (const float*)d_in[29];
    const float* bo_c2 = (const float*)d_in[19];

    float* out     = (float*)d_out;
    float* self_w  = out + (size_t)BB * TT * DD;
    float* cross_w = self_w + (size_t)BB * HH * TT * TT;

    float *QKV, *KVC, *T1, *X1, *X2, *ST, *BS, *BC;
    __nv_bfloat16 *A2, *E2, *FF2, *WT2, *VT2, *VT2C;
    cudaGetSymbolAddress((void**)&QKV,  g_qkv);
    cudaGetSymbolAddress((void**)&KVC,  g_kvc);
    cudaGetSymbolAddress((void**)&T1,   g_t1);
    cudaGetSymbolAddress((void**)&X1,   g_x1);
    cudaGetSymbolAddress((void**)&X2,   g_x2);
    cudaGetSymbolAddress((void**)&ST,   g_st);
    cudaGetSymbolAddress((void**)&BS,   g_bs);
    cudaGetSymbolAddress((void**)&BC,   g_bc);
    cudaGetSymbolAddress((void**)&A2,   g_a2);
    cudaGetSymbolAddress((void**)&E2,   g_e2);
    cudaGetSymbolAddress((void**)&FF2,  g_ff2);
    cudaGetSymbolAddress((void**)&WT2,  g_wt2);
    cudaGetSymbolAddress((void**)&VT2,  g_vt2);
    cudaGetSymbolAddress((void**)&VT2C, g_vt2c);

    cudaFuncSetAttribute(gemm_mma,        cudaFuncAttributeMaxDynamicSharedMemorySize, GEMM_SMEM);
    cudaFuncSetAttribute(attn_scores_mma, cudaFuncAttributeMaxDynamicSharedMemorySize, SCORES_SMEM);
    cudaFuncSetAttribute(attn_av_mma,     cudaFuncAttributeMaxDynamicSharedMemorySize, AV_SMEM);

    const int M = BB * TT;
    dim3 blk(256);
    dim3 gD(DD / 128, M / 128);
    dim3 gQKV(3072 / 128, M / 128);
    dim3 gKV(2048 / 128, M / 128);
    dim3 gF(DFFN / 128, M / 128);
    dim3 scoreG(TT / 128, BB * HH);
    dim3 avG(TT / 64, BB * HH);
    dim3 swG(DD / 128, DD / 32);
    dim3 swG1(DFFN / 128, DD / 32);
    dim3 swG2(DD / 128, DFFN / 32);
    dim3 vtG(TT / 32, DD / 128, BB);
    dim3 lnG(M);
    const int ACT_BLKS = M * DD / 4 / 256;
    float* NC = (float*)0;
    __nv_bfloat16* NO3 = (__nv_bfloat16*)0;

    // ---- fork a second stream for the independent cross-attn prep ----
    cudaStream_t s2;
    cudaStreamCreateWithFlags(&s2, cudaStreamNonBlocking);
    cudaEvent_t e0, e2;
    cudaEventCreateWithFlags(&e0, cudaEventDisableTiming);
    cudaEventCreateWithFlags(&e2, cudaEventDisableTiming);
    cudaEventRecord(e0, 0);
    cudaStreamWaitEvent(s2, e0, 0);

    // ---- stream 2: cross/FFN weight splits + enc pipeline ----
    cudaMemcpyAsync(BC,        bk_c, 1024 * 4, cudaMemcpyDeviceToDevice, s2);
    cudaMemcpyAsync(BC + 1024, bv_c, 1024 * 4, cudaMemcpyDeviceToDevice, s2);
    split_w<<<swG, blk, 0, s2>>>(wk_c, WT2 + 5 * W2D, DD, DD);
    split_w<<<swG, blk, 0, s2>>>(wv_c, WT2 + 6 * W2D, DD, DD);
    split_w<<<swG, blk, 0, s2>>>((const float*)d_in[18], WT2 + 7 * W2D, DD, DD);
    split_w<<<swG1, blk, 0, s2>>>(w1, WT2 + W1OFF, DD, DFFN);
    split_w<<<swG2, blk, 0, s2>>>(w2, WT2 + W2OFF, DFFN, DD);
    split_act<<<ACT_BLKS, blk, 0, s2>>>(enc, E2);
    gemm_mma<<<gKV, blk, GEMM_SMEM, s2>>>(E2, WT2 + 5 * W2D, BC, KVC, NO3, 2048, 1024, 0);
    vt_split<<<vtG, blk, 0, s2>>>(KVC + 1024, 2048, VT2C);
    cudaEventRecord(e2, s2);

    // ---- stream 1 (legacy): self attention chain ----
    cudaMemcpyAsync(BS,        bq_s, 1024 * 4, cudaMemcpyDeviceToDevice);
    cudaMemcpyAsync(BS + 1024, bk_s, 1024 * 4, cudaMemcpyDeviceToDevice);
    cudaMemcpyAsync(BS + 2048, bv_s, 1024 * 4, cudaMemcpyDeviceToDevice);
    split_act<<<ACT_BLKS, blk>>>(x, A2);
    split_w<<<swG, blk>>>(wq_s, WT2 + 0 * W2D, DD, DD);
    split_w<<<swG, blk>>>(wk_s, WT2 + 1 * W2D, DD, DD);
    split_w<<<swG, blk>>>(wv_s, WT2 + 2 * W2D, DD, DD);
    split_w<<<swG, blk>>>(wo_s, WT2 + 3 * W2D, DD, DD);
    split_w<<<swG, blk>>>(wq_c, WT2 + 4 * W2D, DD, DD);
    gemm_mma<<<gQKV, blk, GEMM_SMEM>>>(A2, WT2 + 0 * W2D, BS, QKV, NO3, 3072, 1024, 0);
    vt_split<<<vtG, blk>>>(QKV + 2048, 3072, VT2);
    attn_scores_mma<<<scoreG, blk, SCORES_SMEM>>>(QKV, 3072, QKV + 1024, 3072,
                                                  self_w, ST, src_mask, 1);
    attn_av_mma<<<avG, blk, AV_SMEM>>>(self_w, VT2, ST, src_mask, A2, 1);
    gemm_mma<<<gD, blk, GEMM_SMEM>>>(A2, WT2 + 3 * W2D, bo_s, T1, NO3, DD, 1024, 0);
    add_ln<<<lnG, blk>>>(x, T1, g1, be1, X1, A2);

    // ---- cross attention (join stream 2 before consuming KVC/VT2C/WT2[7+]) ----
    gemm_mma<<<gD, blk, GEMM_SMEM>>>(A2, WT2 + 4 * W2D, bq_c, QKV, NO3, DD, 1024, 0);
    cudaStreamWaitEvent(0, e2, 0);
    attn_scores_mma<<<scoreG, blk, SCORES_SMEM>>>(QKV, 1024, KVC, 2048,
                                                  cross_w, ST, src_mask, 0);
    attn_av_mma<<<avG, blk, AV_SMEM>>>(cross_w, VT2C, ST, src_mask, A2, 0);
    gemm_mma<<<gD, blk, GEMM_SMEM>>>(A2, WT2 + 7 * W2D, bo_c2, T1, NO3, DD, 1024, 0);
    add_ln<<<lnG, blk>>>(X1, T1, g2, be2, X2, A2);

    // ---- feed-forward ----
    gemm_mma<<<gF, blk, GEMM_SMEM>>>(A2, WT2 + W1OFF, b1, NC, FF2, DFFN, 1024, 1);
    gemm_mma<<<gD, blk, GEMM_SMEM>>>(FF2, WT2 + W2OFF, b2, T1, NO3, DD, 4096, 0);
    add_ln<<<lnG, blk>>>(X2, T1, g3, be3, out, NO3);

    cudaEventDestroy(e0);
    cudaEventDestroy(e2);
    cudaStreamDestroy(s2);

    (void)in_sizes; (void)n_in; (void)out_size; (void)bv_c; (void)bq_c;
}